// round 6
// baseline (speedup 1.0000x reference)
#include <cuda_runtime.h>
#include <cuda_bf16.h>
#include <cstdint>

// Problem constants (fixed by the dataset)
constexpr int B  = 8;
constexpr int NN = 10000;
constexpr int E  = 160000;
constexpr int F  = 128;   // GCN feature dim
constexpr int H  = 256;   // hidden dim
constexpr int BNN = B * NN;          // 80000 rows
constexpr float NEG_SLOPE = 0.01f;

// Scratch (allocation-free: __device__ globals)
__device__ float g_dinv[BNN];
__device__ float g_xw [(size_t)BNN * F];
__device__ float g_agg[(size_t)BNN * F];
__device__ float g_h1 [(size_t)BNN * H];

// ---------------------------------------------------------------------------
// Degree kernels
// ---------------------------------------------------------------------------
__global__ void init_deg_kernel() {
    int i = blockIdx.x * blockDim.x + threadIdx.x;
    if (i < BNN) g_dinv[i] = 1.0f;   // self loop
}

__global__ void count_deg_kernel(const int* __restrict__ ei) {
    int i = blockIdx.x * blockDim.x + threadIdx.x;
    if (i >= B * E) return;
    int b = i / E;
    int e = i - b * E;
    int dst = ei[b * 2 * E + E + e];
    atomicAdd(&g_dinv[b * NN + dst], 1.0f);
}

__global__ void rsqrt_deg_kernel() {
    int i = blockIdx.x * blockDim.x + threadIdx.x;
    if (i < BNN) g_dinv[i] = rsqrtf(g_dinv[i]);
}

// ---------------------------------------------------------------------------
// TF32 tensor-core GEMM, double-buffered smem + register prefetch.
// Block tile 128x128x32, 8 warps (2 x 4), warp tile 64x32, mma m16n8k8.
// EPI: 0 = plain, 1 = leaky_relu(+bias), 2 = write C and C2 = dinv^2 * C
// ---------------------------------------------------------------------------
constexpr int BM = 128, BN = 128, BK = 32;
constexpr int AS_W = BM + 1;                 // words per k-row of A stage
constexpr int BS_W = BN + 4;                 // words per k-row of B stage
constexpr int AS_WORDS = BK * AS_W;          // 4128
constexpr int BS_WORDS = BK * BS_W;          // 4224
constexpr int STAGE_WORDS = AS_WORDS + BS_WORDS;   // 8352
constexpr int SMEM_BYTES = 2 * STAGE_WORDS * 4;    // 66816

__device__ __forceinline__ uint32_t f2tf32(float f) {
    uint32_t r;
    asm("cvt.rna.tf32.f32 %0, %1;" : "=r"(r) : "f"(f));
    return r;
}

__device__ __forceinline__ void mma_tf32(float c[4], uint32_t a0, uint32_t a1,
                                         uint32_t a2, uint32_t a3,
                                         uint32_t b0, uint32_t b1) {
    asm volatile(
        "mma.sync.aligned.m16n8k8.row.col.f32.tf32.tf32.f32 "
        "{%0,%1,%2,%3}, {%4,%5,%6,%7}, {%8,%9}, {%0,%1,%2,%3};"
        : "+f"(c[0]), "+f"(c[1]), "+f"(c[2]), "+f"(c[3])
        : "r"(a0), "r"(a1), "r"(a2), "r"(a3), "r"(b0), "r"(b1));
}

template <int EPI>
__global__ __launch_bounds__(256)
void tf32_gemm_kernel(const float* __restrict__ A, const float* __restrict__ Bm,
                      const float* __restrict__ bias, float* __restrict__ C,
                      float* __restrict__ C2, const float* __restrict__ dinv,
                      int M, int Nn, int K) {
    extern __shared__ uint32_t sh[];

    const int tid  = threadIdx.x;
    const int lane = tid & 31;
    const int wid  = tid >> 5;
    const int wm   = wid & 1;   // 2 warps along M
    const int wn   = wid >> 1;  // 4 warps along N

    const int bx = blockIdx.x, by = blockIdx.y;
    const float* Ablk = A + (long long)by * BM * K;
    const float* Bblk = Bm + bx * BN;

    float acc[4][4][4];
    #pragma unroll
    for (int i = 0; i < 4; i++)
        #pragma unroll
        for (int j = 0; j < 4; j++)
            #pragma unroll
            for (int q = 0; q < 4; q++) acc[i][j][q] = 0.0f;

    // A load mapping: 128 rows x 8 float4 (=32 k); 256 threads -> 4 rows each
    const int aR  = tid >> 3;
    const int aC4 = tid & 7;
    // B load mapping: 8 k-rows x 32 float4 per pass; 4 passes
    const int bR  = tid >> 5;
    const int bC4 = tid & 31;

    float4 aReg[4], bReg[4];

    auto load_tile = [&](int kt) {
        #pragma unroll
        for (int r = 0; r < 4; r++)
            aReg[r] = *(const float4*)(Ablk + (long long)(aR + r * 32) * K + kt + aC4 * 4);
        #pragma unroll
        for (int r = 0; r < 4; r++)
            bReg[r] = *(const float4*)(Bblk + (long long)(kt + bR + r * 8) * Nn + bC4 * 4);
    };
    auto store_tile = [&](int st) {
        uint32_t* As = sh + st * STAGE_WORDS;
        uint32_t* Bs = As + AS_WORDS;
        #pragma unroll
        for (int r = 0; r < 4; r++) {
            int row = aR + r * 32;
            As[(aC4 * 4 + 0) * AS_W + row] = f2tf32(aReg[r].x);
            As[(aC4 * 4 + 1) * AS_W + row] = f2tf32(aReg[r].y);
            As[(aC4 * 4 + 2) * AS_W + row] = f2tf32(aReg[r].z);
            As[(aC4 * 4 + 3) * AS_W + row] = f2tf32(aReg[r].w);
        }
        #pragma unroll
        for (int r = 0; r < 4; r++) {
            int row = bR + r * 8;
            Bs[row * BS_W + bC4 * 4 + 0] = f2tf32(bReg[r].x);
            Bs[row * BS_W + bC4 * 4 + 1] = f2tf32(bReg[r].y);
            Bs[row * BS_W + bC4 * 4 + 2] = f2tf32(bReg[r].z);
            Bs[row * BS_W + bC4 * 4 + 3] = f2tf32(bReg[r].w);
        }
    };
    auto compute = [&](int st) {
        const uint32_t* As = sh + st * STAGE_WORDS;
        const uint32_t* Bs = As + AS_WORDS;
        #pragma unroll
        for (int ks = 0; ks < BK; ks += 8) {
            uint32_t af[4][4];
            uint32_t bf[4][2];
            #pragma unroll
            for (int i = 0; i < 4; i++) {
                int mrow = wm * 64 + i * 16 + (lane >> 2);
                af[i][0] = As[(ks + (lane & 3)    ) * AS_W + mrow];
                af[i][1] = As[(ks + (lane & 3)    ) * AS_W + mrow + 8];
                af[i][2] = As[(ks + (lane & 3) + 4) * AS_W + mrow];
                af[i][3] = As[(ks + (lane & 3) + 4) * AS_W + mrow + 8];
            }
            #pragma unroll
            for (int j = 0; j < 4; j++) {
                int ncol = wn * 32 + j * 8 + (lane >> 2);
                bf[j][0] = Bs[(ks + (lane & 3)    ) * BS_W + ncol];
                bf[j][1] = Bs[(ks + (lane & 3) + 4) * BS_W + ncol];
            }
            #pragma unroll
            for (int i = 0; i < 4; i++)
                #pragma unroll
                for (int j = 0; j < 4; j++)
                    mma_tf32(acc[i][j], af[i][0], af[i][1], af[i][2], af[i][3],
                             bf[j][0], bf[j][1]);
        }
    };

    // Double-buffered mainloop: one sync per K-tile
    load_tile(0);
    store_tile(0);
    __syncthreads();
    int stage = 0;
    for (int kt = BK; kt < K; kt += BK) {
        load_tile(kt);            // LDGs in flight
        compute(stage);           // overlap MMA with loads
        store_tile(stage ^ 1);    // fill idle buffer (waits on LDGs)
        __syncthreads();
        stage ^= 1;
    }
    compute(stage);

    // Epilogue
    float* Cblk = C + (long long)by * BM * Nn + bx * BN;
    float* C2blk = (EPI == 2) ? (C2 + (long long)by * BM * Nn + bx * BN) : nullptr;
    #pragma unroll
    for (int i = 0; i < 4; i++) {
        #pragma unroll
        for (int j = 0; j < 4; j++) {
            int col = wn * 32 + j * 8 + 2 * (lane & 3);
            float bx0 = 0.0f, bx1 = 0.0f;
            if (EPI == 1) { bx0 = bias[bx * BN + col]; bx1 = bias[bx * BN + col + 1]; }
            #pragma unroll
            for (int h = 0; h < 2; h++) {
                int row = wm * 64 + i * 16 + (lane >> 2) + h * 8;
                float2 v;
                v.x = acc[i][j][h * 2 + 0] + bx0;
                v.y = acc[i][j][h * 2 + 1] + bx1;
                if (EPI == 1) {
                    v.x = v.x > 0.0f ? v.x : NEG_SLOPE * v.x;
                    v.y = v.y > 0.0f ? v.y : NEG_SLOPE * v.y;
                }
                *(float2*)(Cblk + (long long)row * Nn + col) = v;
                if (EPI == 2) {
                    float d = dinv[by * BM + row];
                    float s = d * d;
                    float2 w; w.x = s * v.x; w.y = s * v.y;
                    *(float2*)(C2blk + (long long)row * Nn + col) = w;
                }
            }
        }
    }
}

// ---------------------------------------------------------------------------
// Edge scatter: one warp per edge, vector red.global.add.v4.f32
// ---------------------------------------------------------------------------
__global__ __launch_bounds__(256)
void scatter_kernel(const int* __restrict__ ei) {
    int gw = (blockIdx.x * blockDim.x + threadIdx.x) >> 5;
    int lane = threadIdx.x & 31;
    if (gw >= B * E) return;
    int b = gw / E;
    int e = gw - b * E;
    const int* eb = ei + b * 2 * E;
    int src = eb[e];
    int dst = eb[E + e];
    float norm = g_dinv[b * NN + src] * g_dinv[b * NN + dst];
    const float4* s = (const float4*)(g_xw + (long long)(b * NN + src) * F);
    float4 v = s[lane];
    float4* d = ((float4*)(g_agg + (long long)(b * NN + dst) * F)) + lane;
    asm volatile("red.global.add.v4.f32 [%0], {%1,%2,%3,%4};"
                 :: "l"(d), "f"(v.x * norm), "f"(v.y * norm),
                    "f"(v.z * norm), "f"(v.w * norm)
                 : "memory");
}

// ---------------------------------------------------------------------------
// Post: out1 = relu(agg + bc) + x0   (written into g_xw, reused)
// ---------------------------------------------------------------------------
__global__ void post_kernel(const float* __restrict__ x0, const float* __restrict__ bc) {
    int i = blockIdx.x * blockDim.x + threadIdx.x;
    if (i >= BNN * (F / 4)) return;
    int c4 = i & (F / 4 - 1);
    float4 a = ((const float4*)g_agg)[i];
    float4 bb = ((const float4*)bc)[c4];
    float4 x = ((const float4*)x0)[i];
    float4 o;
    o.x = fmaxf(a.x + bb.x, 0.0f) + x.x;
    o.y = fmaxf(a.y + bb.y, 0.0f) + x.y;
    o.z = fmaxf(a.z + bb.z, 0.0f) + x.z;
    o.w = fmaxf(a.w + bb.w, 0.0f) + x.w;
    ((float4*)g_xw)[i] = o;
}

// ---------------------------------------------------------------------------
extern "C" void kernel_launch(void* const* d_in, const int* in_sizes, int n_in,
                              void* d_out, int out_size) {
    const float* x0 = (const float*)d_in[0];       // [B,N,F]
    const int*   ei = (const int*)d_in[1];         // [B,2,E] int32
    const float* Wc = (const float*)d_in[2];       // [F,F]
    const float* bc = (const float*)d_in[3];       // [F]
    const float* W1 = (const float*)d_in[4];       // [F,H]
    const float* b1 = (const float*)d_in[5];       // [H]
    const float* W2 = (const float*)d_in[6];       // [H,H]
    const float* b2 = (const float*)d_in[7];       // [H]
    float* out = (float*)d_out;                    // [B,N,H]

    float *xw, *agg, *h1, *dinv;
    cudaGetSymbolAddress((void**)&xw,   g_xw);
    cudaGetSymbolAddress((void**)&agg,  g_agg);
    cudaGetSymbolAddress((void**)&h1,   g_h1);
    cudaGetSymbolAddress((void**)&dinv, g_dinv);

    static bool attr_done = false;
    if (!attr_done) {
        cudaFuncSetAttribute(tf32_gemm_kernel<0>, cudaFuncAttributeMaxDynamicSharedMemorySize, SMEM_BYTES);
        cudaFuncSetAttribute(tf32_gemm_kernel<1>, cudaFuncAttributeMaxDynamicSharedMemorySize, SMEM_BYTES);
        cudaFuncSetAttribute(tf32_gemm_kernel<2>, cudaFuncAttributeMaxDynamicSharedMemorySize, SMEM_BYTES);
        attr_done = true;
    }

    // 1) degrees -> dinv
    init_deg_kernel<<<(BNN + 255) / 256, 256>>>();
    count_deg_kernel<<<(B * E + 255) / 256, 256>>>(ei);
    rsqrt_deg_kernel<<<(BNN + 255) / 256, 256>>>();

    // 2) xw = x0 @ Wc, fused agg = dinv^2 * xw  (M=80000, N=128, K=128)
    {
        dim3 grid(F / BN, BNN / BM);
        tf32_gemm_kernel<2><<<grid, 256, SMEM_BYTES>>>(x0, Wc, nullptr, xw, agg, dinv, BNN, F, F);
    }

    // 3) edge scatter into agg
    scatter_kernel<<<(B * E * 32 + 255) / 256, 256>>>(ei);

    // 4) out1 = relu(agg + bc) + x0  (into g_xw)
    post_kernel<<<(BNN * (F / 4) + 255) / 256, 256>>>(x0, bc);

    // 5) h1 = leaky_relu(out1 @ W1 + b1)  (M=80000, N=256, K=128)
    {
        dim3 grid(H / BN, BNN / BM);
        tf32_gemm_kernel<1><<<grid, 256, SMEM_BYTES>>>(xw, W1, b1, h1, nullptr, nullptr, BNN, H, F);
    }

    // 6) out = leaky_relu(h1 @ W2 + b2)  (M=80000, N=256, K=256)
    {
        dim3 grid(H / BN, BNN / BM);
        tf32_gemm_kernel<1><<<grid, 256, SMEM_BYTES>>>(h1, W2, b2, out, nullptr, nullptr, BNN, H, H);
    }
}

// round 7
// speedup vs baseline: 1.2586x; 1.2586x over previous
#include <cuda_runtime.h>
#include <cuda_bf16.h>
#include <cstdint>

// Problem constants (fixed by the dataset)
constexpr int B  = 8;
constexpr int NN = 10000;
constexpr int E  = 160000;
constexpr int F  = 128;   // GCN feature dim
constexpr int H  = 256;   // hidden dim
constexpr int BNN = B * NN;          // 80000 rows
constexpr float NEG_SLOPE = 0.01f;

// Scratch (allocation-free: __device__ globals)
__device__ float g_dinv[BNN];
__device__ float g_xw [(size_t)BNN * F];
__device__ float g_agg[(size_t)BNN * F];
__device__ float g_h1 [(size_t)BNN * H];

// ---------------------------------------------------------------------------
// Degree kernels
// ---------------------------------------------------------------------------
__global__ void init_deg_kernel() {
    int i = blockIdx.x * blockDim.x + threadIdx.x;
    if (i < BNN) g_dinv[i] = 1.0f;   // self loop
}

__global__ void count_deg_kernel(const int* __restrict__ ei) {
    int i = blockIdx.x * blockDim.x + threadIdx.x;
    if (i >= B * E) return;
    int b = i / E;
    int e = i - b * E;
    int dst = ei[b * 2 * E + E + e];
    atomicAdd(&g_dinv[b * NN + dst], 1.0f);
}

__global__ void rsqrt_deg_kernel() {
    int i = blockIdx.x * blockDim.x + threadIdx.x;
    if (i < BNN) g_dinv[i] = rsqrtf(g_dinv[i]);
}

// ---------------------------------------------------------------------------
// TF32 tensor-core GEMM, ldmatrix fragment path, double-buffered smem.
// Block 128x128x32, 8 warps (2 x 4), warp tile 64x32, mma m16n8k8.
// Smem layouts (per stage): As[m][k] 128x32 tf32 words, Bs[n][k] 128x32,
// both with XOR swizzle: word = row*32 + ((chunk ^ (row&7))<<2) + (k&3),
// chunk = k>>2.  Conflict-free STS.128 and conflict-free LDSM.
// EPI: 1 = leaky_relu(+bias), 2 = write C and C2 = dinv^2 * C
// ---------------------------------------------------------------------------
constexpr int BM = 128, BN = 128, BK = 32;
constexpr int A_WORDS = BM * BK;                  // 4096
constexpr int STAGE_WORDS = 2 * A_WORDS;          // A + B = 8192
constexpr int SMEM_BYTES = 2 * STAGE_WORDS * 4;   // 65536

__device__ __forceinline__ uint32_t f2tf32(float f) {
    uint32_t r;
    asm("cvt.rna.tf32.f32 %0, %1;" : "=r"(r) : "f"(f));
    return r;
}

__device__ __forceinline__ void mma_tf32(float c[4], uint32_t a0, uint32_t a1,
                                         uint32_t a2, uint32_t a3,
                                         uint32_t b0, uint32_t b1) {
    asm volatile(
        "mma.sync.aligned.m16n8k8.row.col.f32.tf32.tf32.f32 "
        "{%0,%1,%2,%3}, {%4,%5,%6,%7}, {%8,%9}, {%0,%1,%2,%3};"
        : "+f"(c[0]), "+f"(c[1]), "+f"(c[2]), "+f"(c[3])
        : "r"(a0), "r"(a1), "r"(a2), "r"(a3), "r"(b0), "r"(b1));
}

__device__ __forceinline__ void ldsm4(uint32_t& r0, uint32_t& r1,
                                      uint32_t& r2, uint32_t& r3, uint32_t addr) {
    asm volatile("ldmatrix.sync.aligned.m8n8.x4.shared.b16 {%0,%1,%2,%3}, [%4];"
                 : "=r"(r0), "=r"(r1), "=r"(r2), "=r"(r3) : "r"(addr));
}

__device__ __forceinline__ void ldsm2(uint32_t& r0, uint32_t& r1, uint32_t addr) {
    asm volatile("ldmatrix.sync.aligned.m8n8.x2.shared.b16 {%0,%1}, [%2];"
                 : "=r"(r0), "=r"(r1) : "r"(addr));
}

template <int EPI>
__global__ __launch_bounds__(256, 2)
void tf32_gemm_kernel(const float* __restrict__ A, const float* __restrict__ Bm,
                      const float* __restrict__ bias, float* __restrict__ C,
                      float* __restrict__ C2, const float* __restrict__ dinv,
                      int M, int Nn, int K) {
    extern __shared__ uint32_t sh[];

    const int tid  = threadIdx.x;
    const int lane = tid & 31;
    const int wid  = tid >> 5;
    const int wm   = wid & 1;   // 2 warps along M
    const int wn   = wid >> 1;  // 4 warps along N

    const int bx = blockIdx.x, by = blockIdx.y;
    const float* Ablk = A + (long long)by * BM * K;
    const float* Bblk = Bm + bx * BN;

    float acc[4][4][4];
    #pragma unroll
    for (int i = 0; i < 4; i++)
        #pragma unroll
        for (int j = 0; j < 4; j++)
            #pragma unroll
            for (int q = 0; q < 4; q++) acc[i][j][q] = 0.0f;

    // A loader: thread -> row aR (4 passes of +32), float4 at k = aC4*4
    const int aR  = tid >> 3;
    const int aC4 = tid & 7;
    // B loader: thread -> col n = bN, 4 k-strided scalar loads (coalesced in n)
    const int bN  = tid & 127;
    const int bKh = tid >> 7;     // 0/1: which 4-k half of the 8-k group

    // Fragment addressing constants (per thread)
    const int m0  = wm * 64 + ((lane >> 3) & 1) * 8 + (lane & 7);
    const int tA  = lane >> 4;          // 0: k_lo chunk, 1: k_hi chunk
    const int m7  = lane & 7;
    const int t16 = lane & 15;
    const int n0  = wn * 32 + (t16 & 7);
    const int tB  = t16 >> 3;
    const int n7  = t16 & 7;

    float4 aReg[4];
    float  bReg[4][4];

    auto load_tile = [&](int kt) {
        #pragma unroll
        for (int r = 0; r < 4; r++)
            aReg[r] = *(const float4*)(Ablk + (long long)(aR + r * 32) * K + kt + aC4 * 4);
        #pragma unroll
        for (int p = 0; p < 4; p++) {
            int k0 = p * 8 + bKh * 4;
            #pragma unroll
            for (int q = 0; q < 4; q++)
                bReg[p][q] = Bblk[(long long)(kt + k0 + q) * Nn + bN];
        }
    };
    auto store_tile = [&](int st) {
        uint32_t* As = sh + st * STAGE_WORDS;
        uint32_t* Bs = As + A_WORDS;
        #pragma unroll
        for (int r = 0; r < 4; r++) {
            int m = aR + r * 32;
            uint32_t* p = As + m * 32 + ((aC4 ^ (m & 7)) << 2);
            *(uint4*)p = make_uint4(f2tf32(aReg[r].x), f2tf32(aReg[r].y),
                                    f2tf32(aReg[r].z), f2tf32(aReg[r].w));
        }
        #pragma unroll
        for (int p = 0; p < 4; p++) {
            int c = (p * 8 + bKh * 4) >> 2;
            uint32_t* q = Bs + bN * 32 + ((c ^ (bN & 7)) << 2);
            *(uint4*)q = make_uint4(f2tf32(bReg[p][0]), f2tf32(bReg[p][1]),
                                    f2tf32(bReg[p][2]), f2tf32(bReg[p][3]));
        }
    };
    auto compute = [&](int st) {
        uint32_t shb = (uint32_t)__cvta_generic_to_shared(sh + st * STAGE_WORDS);
        uint32_t aBase = shb + (m0 << 7);                       // m0 * 128B
        uint32_t bBase = shb + A_WORDS * 4 + (n0 << 7);         // n0 * 128B
        #pragma unroll
        for (int ks = 0; ks < 4; ks++) {
            uint32_t aoff = (uint32_t)(((2 * ks + tA) ^ m7) << 4);
            uint32_t boff = (uint32_t)(((2 * ks + tB) ^ n7) << 4);
            uint32_t af[4][4];
            uint32_t bf[4][2];
            #pragma unroll
            for (int i = 0; i < 4; i++)
                ldsm4(af[i][0], af[i][1], af[i][2], af[i][3],
                      aBase + (i << 11) + aoff);
            #pragma unroll
            for (int j = 0; j < 4; j++)
                ldsm2(bf[j][0], bf[j][1], bBase + (j << 10) + boff);
            #pragma unroll
            for (int i = 0; i < 4; i++)
                #pragma unroll
                for (int j = 0; j < 4; j++)
                    mma_tf32(acc[i][j], af[i][0], af[i][1], af[i][2], af[i][3],
                             bf[j][0], bf[j][1]);
        }
    };

    // Double-buffered mainloop: one sync per K-tile
    load_tile(0);
    store_tile(0);
    __syncthreads();
    int stage = 0;
    for (int kt = BK; kt < K; kt += BK) {
        load_tile(kt);            // LDGs in flight
        compute(stage);
        store_tile(stage ^ 1);
        __syncthreads();
        stage ^= 1;
    }
    compute(stage);

    // Epilogue
    float* Cblk = C + (long long)by * BM * Nn + bx * BN;
    float* C2blk = (EPI == 2) ? (C2 + (long long)by * BM * Nn + bx * BN) : nullptr;
    #pragma unroll
    for (int i = 0; i < 4; i++) {
        #pragma unroll
        for (int j = 0; j < 4; j++) {
            int col = wn * 32 + j * 8 + 2 * (lane & 3);
            float bx0 = 0.0f, bx1 = 0.0f;
            if (EPI == 1) { bx0 = bias[bx * BN + col]; bx1 = bias[bx * BN + col + 1]; }
            #pragma unroll
            for (int h = 0; h < 2; h++) {
                int row = wm * 64 + i * 16 + (lane >> 2) + h * 8;
                float2 v;
                v.x = acc[i][j][h * 2 + 0] + bx0;
                v.y = acc[i][j][h * 2 + 1] + bx1;
                if (EPI == 1) {
                    v.x = v.x > 0.0f ? v.x : NEG_SLOPE * v.x;
                    v.y = v.y > 0.0f ? v.y : NEG_SLOPE * v.y;
                }
                *(float2*)(Cblk + (long long)row * Nn + col) = v;
                if (EPI == 2) {
                    float d = dinv[by * BM + row];
                    float s = d * d;
                    float2 w; w.x = s * v.x; w.y = s * v.y;
                    *(float2*)(C2blk + (long long)row * Nn + col) = w;
                }
            }
        }
    }
}

// ---------------------------------------------------------------------------
// Edge scatter: one warp per edge, vector red.global.add.v4.f32
// ---------------------------------------------------------------------------
__global__ __launch_bounds__(256)
void scatter_kernel(const int* __restrict__ ei) {
    int gw = (blockIdx.x * blockDim.x + threadIdx.x) >> 5;
    int lane = threadIdx.x & 31;
    if (gw >= B * E) return;
    int b = gw / E;
    int e = gw - b * E;
    const int* eb = ei + b * 2 * E;
    int src = eb[e];
    int dst = eb[E + e];
    float norm = g_dinv[b * NN + src] * g_dinv[b * NN + dst];
    const float4* s = (const float4*)(g_xw + (long long)(b * NN + src) * F);
    float4 v = s[lane];
    float4* d = ((float4*)(g_agg + (long long)(b * NN + dst) * F)) + lane;
    asm volatile("red.global.add.v4.f32 [%0], {%1,%2,%3,%4};"
                 :: "l"(d), "f"(v.x * norm), "f"(v.y * norm),
                    "f"(v.z * norm), "f"(v.w * norm)
                 : "memory");
}

// ---------------------------------------------------------------------------
// Post: out1 = relu(agg + bc) + x0   (written into g_xw, reused)
// ---------------------------------------------------------------------------
__global__ void post_kernel(const float* __restrict__ x0, const float* __restrict__ bc) {
    int i = blockIdx.x * blockDim.x + threadIdx.x;
    if (i >= BNN * (F / 4)) return;
    int c4 = i & (F / 4 - 1);
    float4 a = ((const float4*)g_agg)[i];
    float4 bb = ((const float4*)bc)[c4];
    float4 x = ((const float4*)x0)[i];
    float4 o;
    o.x = fmaxf(a.x + bb.x, 0.0f) + x.x;
    o.y = fmaxf(a.y + bb.y, 0.0f) + x.y;
    o.z = fmaxf(a.z + bb.z, 0.0f) + x.z;
    o.w = fmaxf(a.w + bb.w, 0.0f) + x.w;
    ((float4*)g_xw)[i] = o;
}

// ---------------------------------------------------------------------------
extern "C" void kernel_launch(void* const* d_in, const int* in_sizes, int n_in,
                              void* d_out, int out_size) {
    const float* x0 = (const float*)d_in[0];       // [B,N,F]
    const int*   ei = (const int*)d_in[1];         // [B,2,E] int32
    const float* Wc = (const float*)d_in[2];       // [F,F]
    const float* bc = (const float*)d_in[3];       // [F]
    const float* W1 = (const float*)d_in[4];       // [F,H]
    const float* b1 = (const float*)d_in[5];       // [H]
    const float* W2 = (const float*)d_in[6];       // [H,H]
    const float* b2 = (const float*)d_in[7];       // [H]
    float* out = (float*)d_out;                    // [B,N,H]

    float *xw, *agg, *h1, *dinv;
    cudaGetSymbolAddress((void**)&xw,   g_xw);
    cudaGetSymbolAddress((void**)&agg,  g_agg);
    cudaGetSymbolAddress((void**)&h1,   g_h1);
    cudaGetSymbolAddress((void**)&dinv, g_dinv);

    static bool attr_done = false;
    if (!attr_done) {
        cudaFuncSetAttribute(tf32_gemm_kernel<1>, cudaFuncAttributeMaxDynamicSharedMemorySize, SMEM_BYTES);
        cudaFuncSetAttribute(tf32_gemm_kernel<2>, cudaFuncAttributeMaxDynamicSharedMemorySize, SMEM_BYTES);
        attr_done = true;
    }

    // 1) degrees -> dinv
    init_deg_kernel<<<(BNN + 255) / 256, 256>>>();
    count_deg_kernel<<<(B * E + 255) / 256, 256>>>(ei);
    rsqrt_deg_kernel<<<(BNN + 255) / 256, 256>>>();

    // 2) xw = x0 @ Wc, fused agg = dinv^2 * xw  (M=80000, N=128, K=128)
    {
        dim3 grid(F / BN, BNN / BM);
        tf32_gemm_kernel<2><<<grid, 256, SMEM_BYTES>>>(x0, Wc, nullptr, xw, agg, dinv, BNN, F, F);
    }

    // 3) edge scatter into agg
    scatter_kernel<<<(B * E * 32 + 255) / 256, 256>>>(ei);

    // 4) out1 = relu(agg + bc) + x0  (into g_xw)
    post_kernel<<<(BNN * (F / 4) + 255) / 256, 256>>>(x0, bc);

    // 5) h1 = leaky_relu(out1 @ W1 + b1)  (M=80000, N=256, K=128)
    {
        dim3 grid(H / BN, BNN / BM);
        tf32_gemm_kernel<1><<<grid, 256, SMEM_BYTES>>>(xw, W1, b1, h1, nullptr, nullptr, BNN, H, F);
    }

    // 6) out = leaky_relu(h1 @ W2 + b2)  (M=80000, N=256, K=256)
    {
        dim3 grid(H / BN, BNN / BM);
        tf32_gemm_kernel<1><<<grid, 256, SMEM_BYTES>>>(h1, W2, b2, out, nullptr, nullptr, BNN, H, H);
    }
}

// round 9
// speedup vs baseline: 1.3456x; 1.0691x over previous
#include <cuda_runtime.h>
#include <cuda_bf16.h>
#include <cstdint>

// Problem constants (fixed by the dataset)
constexpr int B  = 8;
constexpr int NN = 10000;
constexpr int E  = 160000;
constexpr int F  = 128;   // GCN feature dim
constexpr int H  = 256;   // hidden dim
constexpr int BNN = B * NN;          // 80000 rows
constexpr float NEG_SLOPE = 0.01f;

// Scratch (allocation-free: __device__ globals)
__device__ float    g_dinv[BNN];
__device__ float    g_xw [(size_t)BNN * F];     // fp32 xw (scatter source)
__device__ float    g_agg[(size_t)BNN * F];     // fp32 aggregation target
__device__ uint32_t g_x0t[(size_t)BNN * F];     // tf32 x0
__device__ uint32_t g_o1t[(size_t)BNN * F];     // tf32 out1 = relu(agg+bc)+x0
__device__ uint32_t g_h1t[(size_t)BNN * H];     // tf32 h1
__device__ uint32_t g_wct[F * F];               // Wc^T tf32 [N][K]
__device__ uint32_t g_w1t[H * F];               // W1^T tf32 [N][K]
__device__ uint32_t g_w2t[H * H];               // W2^T tf32 [N][K]

__device__ __forceinline__ uint32_t f2tf32(float f) {
    uint32_t r;
    asm("cvt.rna.tf32.f32 %0, %1;" : "=r"(r) : "f"(f));
    return r;
}

__device__ __forceinline__ void mma_tf32(float c[4], uint32_t a0, uint32_t a1,
                                         uint32_t a2, uint32_t a3,
                                         uint32_t b0, uint32_t b1) {
    asm volatile(
        "mma.sync.aligned.m16n8k8.row.col.f32.tf32.tf32.f32 "
        "{%0,%1,%2,%3}, {%4,%5,%6,%7}, {%8,%9}, {%0,%1,%2,%3};"
        : "+f"(c[0]), "+f"(c[1]), "+f"(c[2]), "+f"(c[3])
        : "r"(a0), "r"(a1), "r"(a2), "r"(a3), "r"(b0), "r"(b1));
}

__device__ __forceinline__ void ldsm4(uint32_t& r0, uint32_t& r1,
                                      uint32_t& r2, uint32_t& r3, uint32_t addr) {
    asm volatile("ldmatrix.sync.aligned.m8n8.x4.shared.b16 {%0,%1,%2,%3}, [%4];"
                 : "=r"(r0), "=r"(r1), "=r"(r2), "=r"(r3) : "r"(addr));
}
__device__ __forceinline__ void ldsm2(uint32_t& r0, uint32_t& r1, uint32_t addr) {
    asm volatile("ldmatrix.sync.aligned.m8n8.x2.shared.b16 {%0,%1}, [%2];"
                 : "=r"(r0), "=r"(r1) : "r"(addr));
}

#define SWZ128(off)   ((off) ^ (((off) >> 3) & 0x70))

// ---------------------------------------------------------------------------
// Degree / conversion kernels
// ---------------------------------------------------------------------------
__global__ void init_deg_kernel() {
    int i = blockIdx.x * blockDim.x + threadIdx.x;
    if (i < BNN) g_dinv[i] = 1.0f;   // self loop
}
__global__ void count_deg_kernel(const int* __restrict__ ei) {
    int i = blockIdx.x * blockDim.x + threadIdx.x;
    if (i >= B * E) return;
    int b = i / E;
    int e = i - b * E;
    int dst = ei[b * 2 * E + E + e];
    atomicAdd(&g_dinv[b * NN + dst], 1.0f);
}
__global__ void rsqrt_deg_kernel() {
    int i = blockIdx.x * blockDim.x + threadIdx.x;
    if (i < BNN) g_dinv[i] = rsqrtf(g_dinv[i]);
}
// W[K][N] -> Wt[N][K] tf32
__global__ void transpose_tf32_kernel(const float* __restrict__ W, uint32_t* __restrict__ Wt,
                                      int K, int N) {
    int i = blockIdx.x * blockDim.x + threadIdx.x;
    if (i >= K * N) return;
    int k = i / N, n = i % N;
    Wt[(size_t)n * K + k] = f2tf32(W[i]);
}
// fp32 -> tf32 bulk convert
__global__ void cvt_tf32_kernel(const float* __restrict__ in, uint32_t* __restrict__ out, int n4) {
    int i = blockIdx.x * blockDim.x + threadIdx.x;
    if (i >= n4) return;
    float4 v = ((const float4*)in)[i];
    ((uint4*)out)[i] = make_uint4(f2tf32(v.x), f2tf32(v.y), f2tf32(v.z), f2tf32(v.w));
}

// ---------------------------------------------------------------------------
// TF32 GEMM, cp.async 3-stage pipeline + ldmatrix fragments.
// All operands pre-converted tf32 in global. Block 128x128x32, 8 warps.
// EPI: 1 = leaky(C+bias) -> tf32 out; 2 = fp32 C and C2 = dinv^2*C; 3 = leaky -> fp32
// ---------------------------------------------------------------------------
constexpr int STAGE_BYTES = 32768;                 // A 16KB + B 16KB
constexpr int GEMM_SMEM   = 3 * STAGE_BYTES;       // 98304

template <int EPI>
__global__ __launch_bounds__(256, 2)
void tf32_gemm_cp_kernel(const uint32_t* __restrict__ At, const uint32_t* __restrict__ Bt,
                         const float* __restrict__ bias, void* __restrict__ Cv,
                         float* __restrict__ C2, const float* __restrict__ dinv,
                         int M, int Nn, int K) {
    extern __shared__ uint32_t sh[];

    const int tid  = threadIdx.x;
    const int lane = tid & 31;
    const int wid  = tid >> 5;
    const int wm   = wid & 1;
    const int wn   = wid >> 1;
    const int bx = blockIdx.x, by = blockIdx.y;

    const uint32_t* Ablk = At + (size_t)by * 128 * K;
    const uint32_t* Bblk = Bt + (size_t)bx * 128 * K;

    float acc[4][4][4];
    #pragma unroll
    for (int i = 0; i < 4; i++)
        #pragma unroll
        for (int j = 0; j < 4; j++)
            #pragma unroll
            for (int q = 0; q < 4; q++) acc[i][j][q] = 0.0f;

    const int sR = tid >> 3;    // 0..31 (4 passes of +32)
    const int sC = tid & 7;     // 16B chunk along k
    const uint32_t sbase = (uint32_t)__cvta_generic_to_shared(sh);

    // Fragment addressing (validated in R7)
    const int m0  = wm * 64 + ((lane >> 3) & 1) * 8 + (lane & 7);
    const int tA  = lane >> 4;
    const int m7  = lane & 7;
    const int t16 = lane & 15;
    const int n0  = wn * 32 + (t16 & 7);
    const int tB  = t16 >> 3;
    const int n7  = t16 & 7;

    auto issue = [&](int st, int kt) {
        uint32_t abase = sbase + st * STAGE_BYTES;
        uint32_t bbase = abase + 16384;
        #pragma unroll
        for (int r = 0; r < 4; r++) {
            int row = sR + r * 32;
            uint32_t dst = abase + SWZ128(row * 128 + sC * 16);
            const uint32_t* src = Ablk + (size_t)row * K + kt + sC * 4;
            asm volatile("cp.async.cg.shared.global [%0], [%1], 16;" :: "r"(dst), "l"(src));
        }
        #pragma unroll
        for (int r = 0; r < 4; r++) {
            int row = sR + r * 32;
            uint32_t dst = bbase + SWZ128(row * 128 + sC * 16);
            const uint32_t* src = Bblk + (size_t)row * K + kt + sC * 4;
            asm volatile("cp.async.cg.shared.global [%0], [%1], 16;" :: "r"(dst), "l"(src));
        }
    };
    auto compute = [&](int st) {
        uint32_t shb = sbase + st * STAGE_BYTES;
        uint32_t aBase = shb + (m0 << 7);
        uint32_t bBase = shb + 16384 + (n0 << 7);
        #pragma unroll
        for (int ks = 0; ks < 4; ks++) {
            uint32_t aoff = (uint32_t)(((2 * ks + tA) ^ m7) << 4);
            uint32_t boff = (uint32_t)(((2 * ks + tB) ^ n7) << 4);
            uint32_t af[4][4];
            uint32_t bf[4][2];
            #pragma unroll
            for (int i = 0; i < 4; i++)
                ldsm4(af[i][0], af[i][1], af[i][2], af[i][3], aBase + (i << 11) + aoff);
            #pragma unroll
            for (int j = 0; j < 4; j++)
                ldsm2(bf[j][0], bf[j][1], bBase + (j << 10) + boff);
            #pragma unroll
            for (int i = 0; i < 4; i++)
                #pragma unroll
                for (int j = 0; j < 4; j++)
                    mma_tf32(acc[i][j], af[i][0], af[i][1], af[i][2], af[i][3],
                             bf[j][0], bf[j][1]);
        }
    };

    const int CH = K / 32;
    issue(0, 0);
    asm volatile("cp.async.commit_group;" ::: "memory");
    if (CH > 1) issue(1, 32);
    asm volatile("cp.async.commit_group;" ::: "memory");

    for (int c = 0; c < CH; c++) {
        asm volatile("cp.async.wait_group 1;" ::: "memory");
        __syncthreads();
        if (c + 2 < CH) issue((c + 2) % 3, (c + 2) * 32);
        asm volatile("cp.async.commit_group;" ::: "memory");
        compute(c % 3);
    }

    // Epilogue
    #pragma unroll
    for (int i = 0; i < 4; i++) {
        #pragma unroll
        for (int j = 0; j < 4; j++) {
            int col = wn * 32 + j * 8 + 2 * (lane & 3);
            float bx0 = 0.0f, bx1 = 0.0f;
            if (EPI != 2) { bx0 = bias[bx * 128 + col]; bx1 = bias[bx * 128 + col + 1]; }
            #pragma unroll
            for (int h = 0; h < 2; h++) {
                int row = wm * 64 + i * 16 + (lane >> 2) + h * 8;
                float vx = acc[i][j][h * 2 + 0] + bx0;
                float vy = acc[i][j][h * 2 + 1] + bx1;
                size_t idx = (size_t)(by * 128 + row) * Nn + bx * 128 + col;
                if (EPI == 2) {
                    float* C = (float*)Cv;
                    *(float2*)(C + idx) = make_float2(vx, vy);
                    float dd = dinv[by * 128 + row];
                    float s = dd * dd;
                    *(float2*)(C2 + idx) = make_float2(s * vx, s * vy);
                } else {
                    vx = vx > 0.0f ? vx : NEG_SLOPE * vx;
                    vy = vy > 0.0f ? vy : NEG_SLOPE * vy;
                    if (EPI == 1) {
                        uint32_t* C = (uint32_t*)Cv;
                        *(uint2*)(C + idx) = make_uint2(f2tf32(vx), f2tf32(vy));
                    } else {
                        float* C = (float*)Cv;
                        *(float2*)(C + idx) = make_float2(vx, vy);
                    }
                }
            }
        }
    }
}

// ---------------------------------------------------------------------------
// Edge scatter: one warp per edge, vector red.global.add.v4.f32
// ---------------------------------------------------------------------------
__global__ __launch_bounds__(256)
void scatter_kernel(const int* __restrict__ ei) {
    int gw = (blockIdx.x * blockDim.x + threadIdx.x) >> 5;
    int lane = threadIdx.x & 31;
    if (gw >= B * E) return;
    int b = gw / E;
    int e = gw - b * E;
    const int* eb = ei + b * 2 * E;
    int src = eb[e];
    int dst = eb[E + e];
    float norm = g_dinv[b * NN + src] * g_dinv[b * NN + dst];
    const float4* s = (const float4*)(g_xw + (long long)(b * NN + src) * F);
    float4 v = s[lane];
    float4* d = ((float4*)(g_agg + (long long)(b * NN + dst) * F)) + lane;
    asm volatile("red.global.add.v4.f32 [%0], {%1,%2,%3,%4};"
                 :: "l"(d), "f"(v.x * norm), "f"(v.y * norm),
                    "f"(v.z * norm), "f"(v.w * norm)
                 : "memory");
}

// ---------------------------------------------------------------------------
// Post: out1 = relu(agg + bc) + x0  -> tf32 into g_o1t
// ---------------------------------------------------------------------------
__global__ void post_kernel(const float* __restrict__ x0, const float* __restrict__ bc) {
    int i = blockIdx.x * blockDim.x + threadIdx.x;
    if (i >= BNN * (F / 4)) return;
    int c4 = i & (F / 4 - 1);
    float4 a = ((const float4*)g_agg)[i];
    float4 bb = ((const float4*)bc)[c4];
    float4 x = ((const float4*)x0)[i];
    float ox = fmaxf(a.x + bb.x, 0.0f) + x.x;
    float oy = fmaxf(a.y + bb.y, 0.0f) + x.y;
    float oz = fmaxf(a.z + bb.z, 0.0f) + x.z;
    float ow = fmaxf(a.w + bb.w, 0.0f) + x.w;
    ((uint4*)g_o1t)[i] = make_uint4(f2tf32(ox), f2tf32(oy), f2tf32(oz), f2tf32(ow));
}

// ---------------------------------------------------------------------------
extern "C" void kernel_launch(void* const* d_in, const int* in_sizes, int n_in,
                              void* d_out, int out_size) {
    const float* x0 = (const float*)d_in[0];       // [B,N,F]
    const int*   ei = (const int*)d_in[1];         // [B,2,E] int32
    const float* Wc = (const float*)d_in[2];       // [F,F]
    const float* bc = (const float*)d_in[3];       // [F]
    const float* W1 = (const float*)d_in[4];       // [F,H]
    const float* b1 = (const float*)d_in[5];       // [H]
    const float* W2 = (const float*)d_in[6];       // [H,H]
    const float* b2 = (const float*)d_in[7];       // [H]
    float* out = (float*)d_out;                    // [B,N,H]

    float *xw, *agg, *dinv;
    uint32_t *x0t, *o1t, *h1t, *wct, *w1t, *w2t;
    cudaGetSymbolAddress((void**)&xw,   g_xw);
    cudaGetSymbolAddress((void**)&agg,  g_agg);
    cudaGetSymbolAddress((void**)&dinv, g_dinv);
    cudaGetSymbolAddress((void**)&x0t,  g_x0t);
    cudaGetSymbolAddress((void**)&o1t,  g_o1t);
    cudaGetSymbolAddress((void**)&h1t,  g_h1t);
    cudaGetSymbolAddress((void**)&wct,  g_wct);
    cudaGetSymbolAddress((void**)&w1t,  g_w1t);
    cudaGetSymbolAddress((void**)&w2t,  g_w2t);

    static bool attr_done = false;
    if (!attr_done) {
        cudaFuncSetAttribute(tf32_gemm_cp_kernel<1>, cudaFuncAttributeMaxDynamicSharedMemorySize, GEMM_SMEM);
        cudaFuncSetAttribute(tf32_gemm_cp_kernel<2>, cudaFuncAttributeMaxDynamicSharedMemorySize, GEMM_SMEM);
        cudaFuncSetAttribute(tf32_gemm_cp_kernel<3>, cudaFuncAttributeMaxDynamicSharedMemorySize, GEMM_SMEM);
        attr_done = true;
    }

    // 0) operand preparation
    transpose_tf32_kernel<<<(F * F + 255) / 256, 256>>>(Wc, wct, F, F);
    transpose_tf32_kernel<<<(F * H + 255) / 256, 256>>>(W1, w1t, F, H);
    transpose_tf32_kernel<<<(H * H + 255) / 256, 256>>>(W2, w2t, H, H);
    cvt_tf32_kernel<<<(BNN * F / 4 + 255) / 256, 256>>>(x0, x0t, BNN * F / 4);

    // 1) degrees -> dinv
    init_deg_kernel<<<(BNN + 255) / 256, 256>>>();
    count_deg_kernel<<<(B * E + 255) / 256, 256>>>(ei);
    rsqrt_deg_kernel<<<(BNN + 255) / 256, 256>>>();

    // 2) xw = x0 @ Wc (fp32) + agg = dinv^2*xw  (M=80000, N=128, K=128)
    {
        dim3 grid(1, BNN / 128);
        tf32_gemm_cp_kernel<2><<<grid, 256, GEMM_SMEM>>>(x0t, wct, nullptr, xw, agg, dinv, BNN, F, F);
    }

    // 3) edge scatter into agg
    scatter_kernel<<<(B * E * 32 + 255) / 256, 256>>>(ei);

    // 4) out1 = relu(agg + bc) + x0  -> tf32 g_o1t
    post_kernel<<<(BNN * (F / 4) + 255) / 256, 256>>>(x0, bc);

    // 5) h1 = leaky_relu(out1 @ W1 + b1) -> tf32 g_h1t  (N=256, K=128)
    {
        dim3 grid(H / 128, BNN / 128);
        tf32_gemm_cp_kernel<1><<<grid, 256, GEMM_SMEM>>>(o1t, w1t, b1, h1t, nullptr, nullptr, BNN, H, F);
    }

    // 6) out = leaky_relu(h1 @ W2 + b2) -> fp32  (N=256, K=256)
    {
        dim3 grid(H / 128, BNN / 128);
        tf32_gemm_cp_kernel<3><<<grid, 256, GEMM_SMEM>>>(h1t, w2t, b2, out, nullptr, nullptr, BNN, H, H);
    }
}

// round 10
// speedup vs baseline: 1.5265x; 1.1345x over previous
#include <cuda_runtime.h>
#include <cuda_fp16.h>
#include <cstdint>

// Problem constants (fixed by the dataset)
constexpr int B  = 8;
constexpr int NN = 10000;
constexpr int E  = 160000;
constexpr int F  = 128;   // GCN feature dim
constexpr int H  = 256;   // hidden dim
constexpr int BNN = B * NN;          // 80000 rows
constexpr float NEG_SLOPE = 0.01f;

// Scratch (allocation-free: __device__ globals)
__device__ float  g_dinv[BNN];
__device__ float  g_xw [(size_t)BNN * F];     // fp32 xw (scatter source)
__device__ float  g_agg[(size_t)BNN * F];     // fp32 aggregation target
__device__ __half g_x0h[(size_t)BNN * F];     // fp16 x0
__device__ __half g_o1h[(size_t)BNN * F];     // fp16 out1
__device__ __half g_h1h[(size_t)BNN * H];     // fp16 h1
__device__ __half g_wch[F * F];               // Wc^T fp16 [N][K]
__device__ __half g_w1h[H * F];               // W1^T fp16 [N][K]
__device__ __half g_w2h[H * H];               // W2^T fp16 [N][K]

__device__ __forceinline__ void mma_f16(float c[4], uint32_t a0, uint32_t a1,
                                        uint32_t a2, uint32_t a3,
                                        uint32_t b0, uint32_t b1) {
    asm volatile(
        "mma.sync.aligned.m16n8k16.row.col.f32.f16.f16.f32 "
        "{%0,%1,%2,%3}, {%4,%5,%6,%7}, {%8,%9}, {%0,%1,%2,%3};"
        : "+f"(c[0]), "+f"(c[1]), "+f"(c[2]), "+f"(c[3])
        : "r"(a0), "r"(a1), "r"(a2), "r"(a3), "r"(b0), "r"(b1));
}

__device__ __forceinline__ void ldsm4(uint32_t& r0, uint32_t& r1,
                                      uint32_t& r2, uint32_t& r3, uint32_t addr) {
    asm volatile("ldmatrix.sync.aligned.m8n8.x4.shared.b16 {%0,%1,%2,%3}, [%4];"
                 : "=r"(r0), "=r"(r1), "=r"(r2), "=r"(r3) : "r"(addr));
}
__device__ __forceinline__ void ldsm2(uint32_t& r0, uint32_t& r1, uint32_t addr) {
    asm volatile("ldmatrix.sync.aligned.m8n8.x2.shared.b16 {%0,%1}, [%2];"
                 : "=r"(r0), "=r"(r1) : "r"(addr));
}

// ---------------------------------------------------------------------------
// Degree / conversion kernels
// ---------------------------------------------------------------------------
__global__ void init_deg_kernel() {
    int i = blockIdx.x * blockDim.x + threadIdx.x;
    if (i < BNN) g_dinv[i] = 1.0f;   // self loop
}
__global__ void count_deg_kernel(const int* __restrict__ ei) {
    int i = blockIdx.x * blockDim.x + threadIdx.x;
    if (i >= B * E) return;
    int b = i / E;
    int e = i - b * E;
    int dst = ei[b * 2 * E + E + e];
    atomicAdd(&g_dinv[b * NN + dst], 1.0f);
}
__global__ void rsqrt_deg_kernel() {
    int i = blockIdx.x * blockDim.x + threadIdx.x;
    if (i < BNN) g_dinv[i] = rsqrtf(g_dinv[i]);
}
// W[K][N] -> Wt[N][K] fp16
__global__ void transpose_f16_kernel(const float* __restrict__ W, __half* __restrict__ Wt,
                                     int K, int N) {
    int i = blockIdx.x * blockDim.x + threadIdx.x;
    if (i >= K * N) return;
    int k = i / N, n = i % N;
    Wt[(size_t)n * K + k] = __float2half_rn(W[i]);
}
// fp32 -> fp16 bulk convert
__global__ void cvt_f16_kernel(const float* __restrict__ in, __half* __restrict__ out, int n4) {
    int i = blockIdx.x * blockDim.x + threadIdx.x;
    if (i >= n4) return;
    float4 v = ((const float4*)in)[i];
    __half2 h01 = __floats2half2_rn(v.x, v.y);
    __half2 h23 = __floats2half2_rn(v.z, v.w);
    uint2 st;
    st.x = *(uint32_t*)&h01;
    st.y = *(uint32_t*)&h23;
    ((uint2*)out)[i] = st;
}

// ---------------------------------------------------------------------------
// FP16 GEMM, cp.async 3-stage pipeline + ldmatrix b16 fragments.
// Block 128x128x32, 8 warps (2 x 4), warp tile 64x32, mma m16n8k16.
// Smem per stage: A 128 rows x 64B + B 128 rows x 64B = 16 KB.
// Swizzle: 16B chunk c of row r stored at c ^ ((r>>1)&3).
// EPI: 1 = leaky(C+bias) -> fp16 out; 2 = fp32 C and C2 = dinv^2*C; 3 = leaky -> fp32
// ---------------------------------------------------------------------------
constexpr int STAGE_BYTES = 16384;
constexpr int GEMM_SMEM   = 3 * STAGE_BYTES;       // 49152

template <int EPI>
__global__ __launch_bounds__(256, 2)
void f16_gemm_kernel(const __half* __restrict__ At, const __half* __restrict__ Bt,
                     const float* __restrict__ bias, void* __restrict__ Cv,
                     float* __restrict__ C2, const float* __restrict__ dinv,
                     int M, int Nn, int K) {
    extern __shared__ uint32_t sh[];

    const int tid  = threadIdx.x;
    const int lane = tid & 31;
    const int wid  = tid >> 5;
    const int wm   = wid & 1;
    const int wn   = wid >> 1;
    const int bx = blockIdx.x, by = blockIdx.y;

    const __half* Ablk = At + (size_t)by * 128 * K;
    const __half* Bblk = Bt + (size_t)bx * 128 * K;

    float acc[4][4][4];
    #pragma unroll
    for (int i = 0; i < 4; i++)
        #pragma unroll
        for (int j = 0; j < 4; j++)
            #pragma unroll
            for (int q = 0; q < 4; q++) acc[i][j][q] = 0.0f;

    const uint32_t sbase = (uint32_t)__cvta_generic_to_shared(sh);
    const int sRow = tid >> 1;          // 0..127
    const int sC2  = (tid & 1) * 2;     // chunk base 0 or 2

    auto issue = [&](int st, int kt) {
        uint32_t abase = sbase + st * STAGE_BYTES;
        uint32_t bbase = abase + 8192;
        #pragma unroll
        for (int q = 0; q < 2; q++) {
            int c = sC2 + q;
            uint32_t doff = sRow * 64 + ((c ^ ((sRow >> 1) & 3)) << 4);
            const __half* srcA = Ablk + (size_t)sRow * K + kt + c * 8;
            asm volatile("cp.async.cg.shared.global [%0], [%1], 16;"
                         :: "r"(abase + doff), "l"(srcA));
            const __half* srcB = Bblk + (size_t)sRow * K + kt + c * 8;
            asm volatile("cp.async.cg.shared.global [%0], [%1], 16;"
                         :: "r"(bbase + doff), "l"(srcB));
        }
    };
    auto compute = [&](int st) {
        uint32_t abase = sbase + st * STAGE_BYTES;
        uint32_t bbase = abase + 8192;
        #pragma unroll
        for (int s = 0; s < 2; s++) {          // two k16 steps per 32-k tile
            uint32_t af[4][4];
            uint32_t bf[4][2];
            #pragma unroll
            for (int i = 0; i < 4; i++) {
                int row = wm * 64 + i * 16 + (lane & 7) + ((lane >> 3) & 1) * 8;
                int ch  = 2 * s + (lane >> 4);
                uint32_t addr = abase + row * 64 + ((ch ^ ((row >> 1) & 3)) << 4);
                ldsm4(af[i][0], af[i][1], af[i][2], af[i][3], addr);
            }
            #pragma unroll
            for (int j = 0; j < 4; j++) {
                int row = wn * 32 + j * 8 + (lane & 7);
                int ch  = 2 * s + ((lane >> 3) & 1);
                uint32_t addr = bbase + row * 64 + ((ch ^ ((row >> 1) & 3)) << 4);
                ldsm2(bf[j][0], bf[j][1], addr);
            }
            #pragma unroll
            for (int i = 0; i < 4; i++)
                #pragma unroll
                for (int j = 0; j < 4; j++)
                    mma_f16(acc[i][j], af[i][0], af[i][1], af[i][2], af[i][3],
                            bf[j][0], bf[j][1]);
        }
    };

    const int CH = K / 32;
    issue(0, 0);
    asm volatile("cp.async.commit_group;" ::: "memory");
    if (CH > 1) issue(1, 32);
    asm volatile("cp.async.commit_group;" ::: "memory");

    for (int c = 0; c < CH; c++) {
        asm volatile("cp.async.wait_group 1;" ::: "memory");
        __syncthreads();
        if (c + 2 < CH) issue((c + 2) % 3, (c + 2) * 32);
        asm volatile("cp.async.commit_group;" ::: "memory");
        compute(c % 3);
    }

    // Epilogue (C fragment: rows (lane>>2)+{0,8}, cols 2*(lane&3)+{0,1})
    #pragma unroll
    for (int i = 0; i < 4; i++) {
        #pragma unroll
        for (int j = 0; j < 4; j++) {
            int col = wn * 32 + j * 8 + 2 * (lane & 3);
            float bx0 = 0.0f, bx1 = 0.0f;
            if (EPI != 2) { bx0 = bias[bx * 128 + col]; bx1 = bias[bx * 128 + col + 1]; }
            #pragma unroll
            for (int h = 0; h < 2; h++) {
                int row = wm * 64 + i * 16 + (lane >> 2) + h * 8;
                float vx = acc[i][j][h * 2 + 0] + bx0;
                float vy = acc[i][j][h * 2 + 1] + bx1;
                size_t idx = (size_t)(by * 128 + row) * Nn + bx * 128 + col;
                if (EPI == 2) {
                    float* C = (float*)Cv;
                    *(float2*)(C + idx) = make_float2(vx, vy);
                    float dd = dinv[by * 128 + row];
                    float s = dd * dd;
                    *(float2*)(C2 + idx) = make_float2(s * vx, s * vy);
                } else {
                    vx = vx > 0.0f ? vx : NEG_SLOPE * vx;
                    vy = vy > 0.0f ? vy : NEG_SLOPE * vy;
                    if (EPI == 1) {
                        __half2 hv = __floats2half2_rn(vx, vy);
                        *(uint32_t*)((__half*)Cv + idx) = *(uint32_t*)&hv;
                    } else {
                        float* C = (float*)Cv;
                        *(float2*)(C + idx) = make_float2(vx, vy);
                    }
                }
            }
        }
    }
}

// ---------------------------------------------------------------------------
// Edge scatter: one warp per edge, vector red.global.add.v4.f32
// ---------------------------------------------------------------------------
__global__ __launch_bounds__(256)
void scatter_kernel(const int* __restrict__ ei) {
    int gw = (blockIdx.x * blockDim.x + threadIdx.x) >> 5;
    int lane = threadIdx.x & 31;
    if (gw >= B * E) return;
    int b = gw / E;
    int e = gw - b * E;
    const int* eb = ei + b * 2 * E;
    int src = eb[e];
    int dst = eb[E + e];
    float norm = g_dinv[b * NN + src] * g_dinv[b * NN + dst];
    const float4* s = (const float4*)(g_xw + (long long)(b * NN + src) * F);
    float4 v = s[lane];
    float4* d = ((float4*)(g_agg + (long long)(b * NN + dst) * F)) + lane;
    asm volatile("red.global.add.v4.f32 [%0], {%1,%2,%3,%4};"
                 :: "l"(d), "f"(v.x * norm), "f"(v.y * norm),
                    "f"(v.z * norm), "f"(v.w * norm)
                 : "memory");
}

// ---------------------------------------------------------------------------
// Post: out1 = relu(agg + bc) + x0  -> fp16 into g_o1h
// ---------------------------------------------------------------------------
__global__ void post_kernel(const float* __restrict__ x0, const float* __restrict__ bc) {
    int i = blockIdx.x * blockDim.x + threadIdx.x;
    if (i >= BNN * (F / 4)) return;
    int c4 = i & (F / 4 - 1);
    float4 a = ((const float4*)g_agg)[i];
    float4 bb = ((const float4*)bc)[c4];
    float4 x = ((const float4*)x0)[i];
    float ox = fmaxf(a.x + bb.x, 0.0f) + x.x;
    float oy = fmaxf(a.y + bb.y, 0.0f) + x.y;
    float oz = fmaxf(a.z + bb.z, 0.0f) + x.z;
    float ow = fmaxf(a.w + bb.w, 0.0f) + x.w;
    __half2 h01 = __floats2half2_rn(ox, oy);
    __half2 h23 = __floats2half2_rn(oz, ow);
    uint2 st;
    st.x = *(uint32_t*)&h01;
    st.y = *(uint32_t*)&h23;
    ((uint2*)g_o1h)[i] = st;
}

// ---------------------------------------------------------------------------
extern "C" void kernel_launch(void* const* d_in, const int* in_sizes, int n_in,
                              void* d_out, int out_size) {
    const float* x0 = (const float*)d_in[0];       // [B,N,F]
    const int*   ei = (const int*)d_in[1];         // [B,2,E] int32
    const float* Wc = (const float*)d_in[2];       // [F,F]
    const float* bc = (const float*)d_in[3];       // [F]
    const float* W1 = (const float*)d_in[4];       // [F,H]
    const float* b1 = (const float*)d_in[5];       // [H]
    const float* W2 = (const float*)d_in[6];       // [H,H]
    const float* b2 = (const float*)d_in[7];       // [H]
    float* out = (float*)d_out;                    // [B,N,H]

    float *xw, *agg, *dinv;
    __half *x0h, *o1h, *h1h, *wch, *w1h, *w2h;
    cudaGetSymbolAddress((void**)&xw,   g_xw);
    cudaGetSymbolAddress((void**)&agg,  g_agg);
    cudaGetSymbolAddress((void**)&dinv, g_dinv);
    cudaGetSymbolAddress((void**)&x0h,  g_x0h);
    cudaGetSymbolAddress((void**)&o1h,  g_o1h);
    cudaGetSymbolAddress((void**)&h1h,  g_h1h);
    cudaGetSymbolAddress((void**)&wch,  g_wch);
    cudaGetSymbolAddress((void**)&w1h,  g_w1h);
    cudaGetSymbolAddress((void**)&w2h,  g_w2h);

    static bool attr_done = false;
    if (!attr_done) {
        cudaFuncSetAttribute(f16_gemm_kernel<1>, cudaFuncAttributeMaxDynamicSharedMemorySize, GEMM_SMEM);
        cudaFuncSetAttribute(f16_gemm_kernel<2>, cudaFuncAttributeMaxDynamicSharedMemorySize, GEMM_SMEM);
        cudaFuncSetAttribute(f16_gemm_kernel<3>, cudaFuncAttributeMaxDynamicSharedMemorySize, GEMM_SMEM);
        attr_done = true;
    }

    // 0) operand preparation (fp16)
    transpose_f16_kernel<<<(F * F + 255) / 256, 256>>>(Wc, wch, F, F);
    transpose_f16_kernel<<<(F * H + 255) / 256, 256>>>(W1, w1h, F, H);
    transpose_f16_kernel<<<(H * H + 255) / 256, 256>>>(W2, w2h, H, H);
    cvt_f16_kernel<<<(BNN * F / 4 + 255) / 256, 256>>>(x0, x0h, BNN * F / 4);

    // 1) degrees -> dinv
    init_deg_kernel<<<(BNN + 255) / 256, 256>>>();
    count_deg_kernel<<<(B * E + 255) / 256, 256>>>(ei);
    rsqrt_deg_kernel<<<(BNN + 255) / 256, 256>>>();

    // 2) xw = x0 @ Wc (fp32) + agg = dinv^2*xw  (M=80000, N=128, K=128)
    {
        dim3 grid(1, BNN / 128);
        f16_gemm_kernel<2><<<grid, 256, GEMM_SMEM>>>(x0h, wch, nullptr, xw, agg, dinv, BNN, F, F);
    }

    // 3) edge scatter into agg
    scatter_kernel<<<(B * E * 32 + 255) / 256, 256>>>(ei);

    // 4) out1 = relu(agg + bc) + x0  -> fp16 g_o1h
    post_kernel<<<(BNN * (F / 4) + 255) / 256, 256>>>(x0, bc);

    // 5) h1 = leaky_relu(out1 @ W1 + b1) -> fp16 g_h1h  (N=256, K=128)
    {
        dim3 grid(H / 128, BNN / 128);
        f16_gemm_kernel<1><<<grid, 256, GEMM_SMEM>>>(o1h, w1h, b1, h1h, nullptr, nullptr, BNN, H, F);
    }

    // 6) out = leaky_relu(h1 @ W2 + b2) -> fp32  (N=256, K=256)
    {
        dim3 grid(H / 128, BNN / 128);
        f16_gemm_kernel<3><<<grid, 256, GEMM_SMEM>>>(h1h, w2h, b2, out, nullptr, nullptr, BNN, H, H);
    }
}

// round 11
// speedup vs baseline: 1.5963x; 1.0457x over previous
#include <cuda_runtime.h>
#include <cuda_fp16.h>
#include <cstdint>

// Problem constants (fixed by the dataset)
constexpr int B  = 8;
constexpr int NN = 10000;
constexpr int E  = 160000;
constexpr int F  = 128;   // GCN feature dim
constexpr int H  = 256;   // hidden dim
constexpr int BNN = B * NN;          // 80000 rows
constexpr float NEG_SLOPE = 0.01f;

// Scratch (allocation-free: __device__ globals)
__device__ float  g_dinv[BNN];
__device__ float  g_agg[(size_t)BNN * F];     // fp32 aggregation target
__device__ __half g_xwh[(size_t)BNN * F];     // fp16 xw (scatter source)
__device__ __half g_x0h[(size_t)BNN * F];     // fp16 x0
__device__ __half g_o1h[(size_t)BNN * F];     // fp16 out1
__device__ __half g_h1h[(size_t)BNN * H];     // fp16 h1
__device__ __half g_wch[F * F];               // Wc^T fp16 [N][K]
__device__ __half g_w1h[H * F];               // W1^T fp16 [N][K]
__device__ __half g_w2h[H * H];               // W2^T fp16 [N][K]

__device__ __forceinline__ void mma_f16(float c[4], uint32_t a0, uint32_t a1,
                                        uint32_t a2, uint32_t a3,
                                        uint32_t b0, uint32_t b1) {
    asm volatile(
        "mma.sync.aligned.m16n8k16.row.col.f32.f16.f16.f32 "
        "{%0,%1,%2,%3}, {%4,%5,%6,%7}, {%8,%9}, {%0,%1,%2,%3};"
        : "+f"(c[0]), "+f"(c[1]), "+f"(c[2]), "+f"(c[3])
        : "r"(a0), "r"(a1), "r"(a2), "r"(a3), "r"(b0), "r"(b1));
}

__device__ __forceinline__ void ldsm4(uint32_t& r0, uint32_t& r1,
                                      uint32_t& r2, uint32_t& r3, uint32_t addr) {
    asm volatile("ldmatrix.sync.aligned.m8n8.x4.shared.b16 {%0,%1,%2,%3}, [%4];"
                 : "=r"(r0), "=r"(r1), "=r"(r2), "=r"(r3) : "r"(addr));
}
__device__ __forceinline__ void ldsm2(uint32_t& r0, uint32_t& r1, uint32_t addr) {
    asm volatile("ldmatrix.sync.aligned.m8n8.x2.shared.b16 {%0,%1}, [%2];"
                 : "=r"(r0), "=r"(r1) : "r"(addr));
}

// ---------------------------------------------------------------------------
// Degree / conversion kernels
// ---------------------------------------------------------------------------
__global__ void init_deg_kernel() {
    int i = blockIdx.x * blockDim.x + threadIdx.x;
    if (i < BNN) g_dinv[i] = 1.0f;   // self loop
}
__global__ void count_deg_kernel(const int* __restrict__ ei) {
    int i = blockIdx.x * blockDim.x + threadIdx.x;
    if (i >= B * E) return;
    int b = i / E;
    int e = i - b * E;
    int dst = ei[b * 2 * E + E + e];
    atomicAdd(&g_dinv[b * NN + dst], 1.0f);
}
__global__ void rsqrt_deg_kernel() {
    int i = blockIdx.x * blockDim.x + threadIdx.x;
    if (i < BNN) g_dinv[i] = rsqrtf(g_dinv[i]);
}
// W[K][N] -> Wt[N][K] fp16
__global__ void transpose_f16_kernel(const float* __restrict__ W, __half* __restrict__ Wt,
                                     int K, int N) {
    int i = blockIdx.x * blockDim.x + threadIdx.x;
    if (i >= K * N) return;
    int k = i / N, n = i % N;
    Wt[(size_t)n * K + k] = __float2half_rn(W[i]);
}
// fp32 -> fp16 bulk convert
__global__ void cvt_f16_kernel(const float* __restrict__ in, __half* __restrict__ out, int n4) {
    int i = blockIdx.x * blockDim.x + threadIdx.x;
    if (i >= n4) return;
    float4 v = ((const float4*)in)[i];
    __half2 h01 = __floats2half2_rn(v.x, v.y);
    __half2 h23 = __floats2half2_rn(v.z, v.w);
    uint2 st;
    st.x = *(uint32_t*)&h01;
    st.y = *(uint32_t*)&h23;
    ((uint2*)out)[i] = st;
}

// ---------------------------------------------------------------------------
// FP16 GEMM, cp.async 3-stage pipeline + ldmatrix b16 fragments.
// Block 128x128x32, 8 warps (2 x 4), warp tile 64x32, mma m16n8k16.
// Smem per stage: A 128 rows x 64B + B 128 rows x 64B = 16 KB.
// Swizzle: 16B chunk c of row r stored at c ^ ((r>>1)&3).
// EPI: 1 = leaky(C+bias) -> fp16 out; 2 = fp16 xw + fp32 agg=dinv^2*C; 3 = leaky -> fp32
// ---------------------------------------------------------------------------
constexpr int STAGE_BYTES = 16384;
constexpr int GEMM_SMEM   = 3 * STAGE_BYTES;       // 49152

template <int EPI>
__global__ __launch_bounds__(256, 2)
void f16_gemm_kernel(const __half* __restrict__ At, const __half* __restrict__ Bt,
                     const float* __restrict__ bias, void* __restrict__ Cv,
                     float* __restrict__ C2, const float* __restrict__ dinv,
                     int M, int Nn, int K) {
    extern __shared__ uint32_t sh[];

    const int tid  = threadIdx.x;
    const int lane = tid & 31;
    const int wid  = tid >> 5;
    const int wm   = wid & 1;
    const int wn   = wid >> 1;
    const int bx = blockIdx.x, by = blockIdx.y;

    const __half* Ablk = At + (size_t)by * 128 * K;
    const __half* Bblk = Bt + (size_t)bx * 128 * K;

    float acc[4][4][4];
    #pragma unroll
    for (int i = 0; i < 4; i++)
        #pragma unroll
        for (int j = 0; j < 4; j++)
            #pragma unroll
            for (int q = 0; q < 4; q++) acc[i][j][q] = 0.0f;

    const uint32_t sbase = (uint32_t)__cvta_generic_to_shared(sh);
    const int sRow = tid >> 1;          // 0..127
    const int sC2  = (tid & 1) * 2;     // chunk base 0 or 2

    auto issue = [&](int st, int kt) {
        uint32_t abase = sbase + st * STAGE_BYTES;
        uint32_t bbase = abase + 8192;
        #pragma unroll
        for (int q = 0; q < 2; q++) {
            int c = sC2 + q;
            uint32_t doff = sRow * 64 + ((c ^ ((sRow >> 1) & 3)) << 4);
            const __half* srcA = Ablk + (size_t)sRow * K + kt + c * 8;
            asm volatile("cp.async.cg.shared.global [%0], [%1], 16;"
                         :: "r"(abase + doff), "l"(srcA));
            const __half* srcB = Bblk + (size_t)sRow * K + kt + c * 8;
            asm volatile("cp.async.cg.shared.global [%0], [%1], 16;"
                         :: "r"(bbase + doff), "l"(srcB));
        }
    };
    auto compute = [&](int st) {
        uint32_t abase = sbase + st * STAGE_BYTES;
        uint32_t bbase = abase + 8192;
        #pragma unroll
        for (int s = 0; s < 2; s++) {          // two k16 steps per 32-k tile
            uint32_t af[4][4];
            uint32_t bf[4][2];
            #pragma unroll
            for (int i = 0; i < 4; i++) {
                int row = wm * 64 + i * 16 + (lane & 7) + ((lane >> 3) & 1) * 8;
                int ch  = 2 * s + (lane >> 4);
                uint32_t addr = abase + row * 64 + ((ch ^ ((row >> 1) & 3)) << 4);
                ldsm4(af[i][0], af[i][1], af[i][2], af[i][3], addr);
            }
            #pragma unroll
            for (int j = 0; j < 4; j++) {
                int row = wn * 32 + j * 8 + (lane & 7);
                int ch  = 2 * s + ((lane >> 3) & 1);
                uint32_t addr = bbase + row * 64 + ((ch ^ ((row >> 1) & 3)) << 4);
                ldsm2(bf[j][0], bf[j][1], addr);
            }
            #pragma unroll
            for (int i = 0; i < 4; i++)
                #pragma unroll
                for (int j = 0; j < 4; j++)
                    mma_f16(acc[i][j], af[i][0], af[i][1], af[i][2], af[i][3],
                            bf[j][0], bf[j][1]);
        }
    };

    const int CH = K / 32;
    issue(0, 0);
    asm volatile("cp.async.commit_group;" ::: "memory");
    if (CH > 1) issue(1, 32);
    asm volatile("cp.async.commit_group;" ::: "memory");

    for (int c = 0; c < CH; c++) {
        asm volatile("cp.async.wait_group 1;" ::: "memory");
        __syncthreads();
        if (c + 2 < CH) issue((c + 2) % 3, (c + 2) * 32);
        asm volatile("cp.async.commit_group;" ::: "memory");
        compute(c % 3);
    }

    // Epilogue (C fragment: rows (lane>>2)+{0,8}, cols 2*(lane&3)+{0,1})
    #pragma unroll
    for (int i = 0; i < 4; i++) {
        #pragma unroll
        for (int j = 0; j < 4; j++) {
            int col = wn * 32 + j * 8 + 2 * (lane & 3);
            float bx0 = 0.0f, bx1 = 0.0f;
            if (EPI != 2) { bx0 = bias[bx * 128 + col]; bx1 = bias[bx * 128 + col + 1]; }
            #pragma unroll
            for (int h = 0; h < 2; h++) {
                int row = wm * 64 + i * 16 + (lane >> 2) + h * 8;
                float vx = acc[i][j][h * 2 + 0] + bx0;
                float vy = acc[i][j][h * 2 + 1] + bx1;
                size_t idx = (size_t)(by * 128 + row) * Nn + bx * 128 + col;
                if (EPI == 2) {
                    // fp16 xw for scatter gather + fp32 agg = dinv^2 * xw
                    __half2 hv = __floats2half2_rn(vx, vy);
                    *(uint32_t*)((__half*)Cv + idx) = *(uint32_t*)&hv;
                    float dd = dinv[by * 128 + row];
                    float s = dd * dd;
                    *(float2*)(C2 + idx) = make_float2(s * vx, s * vy);
                } else {
                    vx = vx > 0.0f ? vx : NEG_SLOPE * vx;
                    vy = vy > 0.0f ? vy : NEG_SLOPE * vy;
                    if (EPI == 1) {
                        __half2 hv = __floats2half2_rn(vx, vy);
                        *(uint32_t*)((__half*)Cv + idx) = *(uint32_t*)&hv;
                    } else {
                        float* C = (float*)Cv;
                        *(float2*)(C + idx) = make_float2(vx, vy);
                    }
                }
            }
        }
    }
}

// ---------------------------------------------------------------------------
// Edge scatter: one warp per edge, fp16 gather (8B/lane) + v4 fp32 RED
// ---------------------------------------------------------------------------
__global__ __launch_bounds__(256)
void scatter_kernel(const int* __restrict__ ei) {
    int gw = (blockIdx.x * blockDim.x + threadIdx.x) >> 5;
    int lane = threadIdx.x & 31;
    if (gw >= B * E) return;
    int b = gw / E;
    int e = gw - b * E;
    const int* eb = ei + b * 2 * E;
    int src = eb[e];
    int dst = eb[E + e];
    float norm = g_dinv[b * NN + src] * g_dinv[b * NN + dst];
    const uint2* s = (const uint2*)(g_xwh + (size_t)(b * NN + src) * F);
    uint2 v = s[lane];                      // 4 halfs
    __half2 h01 = *(__half2*)&v.x;
    __half2 h23 = *(__half2*)&v.y;
    float2 f01 = __half22float2(h01);
    float2 f23 = __half22float2(h23);
    float4* d = ((float4*)(g_agg + (size_t)(b * NN + dst) * F)) + lane;
    asm volatile("red.global.add.v4.f32 [%0], {%1,%2,%3,%4};"
                 :: "l"(d), "f"(f01.x * norm), "f"(f01.y * norm),
                    "f"(f23.x * norm), "f"(f23.y * norm)
                 : "memory");
}

// ---------------------------------------------------------------------------
// Post: out1 = relu(agg + bc) + x0h  -> fp16 into g_o1h
// ---------------------------------------------------------------------------
__global__ void post_kernel(const float* __restrict__ bc) {
    int i = blockIdx.x * blockDim.x + threadIdx.x;
    if (i >= BNN * (F / 4)) return;
    int c4 = i & (F / 4 - 1);
    float4 a = ((const float4*)g_agg)[i];
    float4 bb = ((const float4*)bc)[c4];
    uint2 xh = ((const uint2*)g_x0h)[i];
    float2 x01 = __half22float2(*(__half2*)&xh.x);
    float2 x23 = __half22float2(*(__half2*)&xh.y);
    float ox = fmaxf(a.x + bb.x, 0.0f) + x01.x;
    float oy = fmaxf(a.y + bb.y, 0.0f) + x01.y;
    float oz = fmaxf(a.z + bb.z, 0.0f) + x23.x;
    float ow = fmaxf(a.w + bb.w, 0.0f) + x23.y;
    __half2 h01 = __floats2half2_rn(ox, oy);
    __half2 h23 = __floats2half2_rn(oz, ow);
    uint2 st;
    st.x = *(uint32_t*)&h01;
    st.y = *(uint32_t*)&h23;
    ((uint2*)g_o1h)[i] = st;
}

// ---------------------------------------------------------------------------
extern "C" void kernel_launch(void* const* d_in, const int* in_sizes, int n_in,
                              void* d_out, int out_size) {
    const float* x0 = (const float*)d_in[0];       // [B,N,F]
    const int*   ei = (const int*)d_in[1];         // [B,2,E] int32
    const float* Wc = (const float*)d_in[2];       // [F,F]
    const float* bc = (const float*)d_in[3];       // [F]
    const float* W1 = (const float*)d_in[4];       // [F,H]
    const float* b1 = (const float*)d_in[5];       // [H]
    const float* W2 = (const float*)d_in[6];       // [H,H]
    const float* b2 = (const float*)d_in[7];       // [H]
    float* out = (float*)d_out;                    // [B,N,H]

    float *agg, *dinv;
    __half *xwh, *x0h, *o1h, *h1h, *wch, *w1h, *w2h;
    cudaGetSymbolAddress((void**)&agg,  g_agg);
    cudaGetSymbolAddress((void**)&dinv, g_dinv);
    cudaGetSymbolAddress((void**)&xwh,  g_xwh);
    cudaGetSymbolAddress((void**)&x0h,  g_x0h);
    cudaGetSymbolAddress((void**)&o1h,  g_o1h);
    cudaGetSymbolAddress((void**)&h1h,  g_h1h);
    cudaGetSymbolAddress((void**)&wch,  g_wch);
    cudaGetSymbolAddress((void**)&w1h,  g_w1h);
    cudaGetSymbolAddress((void**)&w2h,  g_w2h);

    static bool attr_done = false;
    if (!attr_done) {
        cudaFuncSetAttribute(f16_gemm_kernel<1>, cudaFuncAttributeMaxDynamicSharedMemorySize, GEMM_SMEM);
        cudaFuncSetAttribute(f16_gemm_kernel<2>, cudaFuncAttributeMaxDynamicSharedMemorySize, GEMM_SMEM);
        cudaFuncSetAttribute(f16_gemm_kernel<3>, cudaFuncAttributeMaxDynamicSharedMemorySize, GEMM_SMEM);
        attr_done = true;
    }

    // 0) operand preparation (fp16)
    transpose_f16_kernel<<<(F * F + 255) / 256, 256>>>(Wc, wch, F, F);
    transpose_f16_kernel<<<(F * H + 255) / 256, 256>>>(W1, w1h, F, H);
    transpose_f16_kernel<<<(H * H + 255) / 256, 256>>>(W2, w2h, H, H);
    cvt_f16_kernel<<<(BNN * F / 4 + 255) / 256, 256>>>(x0, x0h, BNN * F / 4);

    // 1) degrees -> dinv
    init_deg_kernel<<<(BNN + 255) / 256, 256>>>();
    count_deg_kernel<<<(B * E + 255) / 256, 256>>>(ei);
    rsqrt_deg_kernel<<<(BNN + 255) / 256, 256>>>();

    // 2) xw = x0 @ Wc (fp16) + agg = dinv^2*xw (fp32)  (M=80000, N=128, K=128)
    {
        dim3 grid(1, BNN / 128);
        f16_gemm_kernel<2><<<grid, 256, GEMM_SMEM>>>(x0h, wch, nullptr, xwh, agg, dinv, BNN, F, F);
    }

    // 3) edge scatter into agg (fp16 gather, fp32 RED)
    scatter_kernel<<<(B * E * 32 + 255) / 256, 256>>>(ei);

    // 4) out1 = relu(agg + bc) + x0h  -> fp16 g_o1h
    post_kernel<<<(BNN * (F / 4) + 255) / 256, 256>>>(bc);

    // 5) h1 = leaky_relu(out1 @ W1 + b1) -> fp16 g_h1h  (N=256, K=128)
    {
        dim3 grid(H / 128, BNN / 128);
        f16_gemm_kernel<1><<<grid, 256, GEMM_SMEM>>>(o1h, w1h, b1, h1h, nullptr, nullptr, BNN, H, F);
    }

    // 6) out = leaky_relu(h1 @ W2 + b2) -> fp32  (N=256, K=256)
    {
        dim3 grid(H / 128, BNN / 128);
        f16_gemm_kernel<3><<<grid, 256, GEMM_SMEM>>>(h1h, w2h, b2, out, nullptr, nullptr, BNN, H, H);
    }
}

// round 12
// speedup vs baseline: 2.2823x; 1.4297x over previous
#include <cuda_runtime.h>
#include <cuda_fp16.h>
#include <cstdint>

// Problem constants (fixed by the dataset)
constexpr int B  = 8;
constexpr int NN = 10000;
constexpr int E  = 160000;
constexpr int F  = 128;   // GCN feature dim
constexpr int H  = 256;   // hidden dim
constexpr int BNN = B * NN;          // 80000 rows
constexpr int BE  = B * E;           // 1.28M edges
constexpr int NBLK = (BNN + 255) / 256;   // 313 scan blocks
constexpr float NEG_SLOPE = 0.01f;

// Scratch (allocation-free: __device__ globals)
__device__ float  g_dinv[BNN];
__device__ int    g_degi[BNN];
__device__ int    g_rowoff[BNN];
__device__ int    g_cursor[BNN];
__device__ int    g_bsum[512];
__device__ int    g_csr_src[BE];
__device__ float  g_csr_norm[BE];
__device__ __half g_xwh[(size_t)BNN * F];     // fp16 xw (gather source)
__device__ __half g_x0h[(size_t)BNN * F];     // fp16 x0
__device__ __half g_o1h[(size_t)BNN * F];     // fp16 out1
__device__ __half g_h1h[(size_t)BNN * H];     // fp16 h1
__device__ __half g_wch[F * F];               // Wc^T fp16 [N][K]
__device__ __half g_w1h[H * F];               // W1^T fp16 [N][K]
__device__ __half g_w2h[H * H];               // W2^T fp16 [N][K]

__device__ __forceinline__ void mma_f16(float c[4], uint32_t a0, uint32_t a1,
                                        uint32_t a2, uint32_t a3,
                                        uint32_t b0, uint32_t b1) {
    asm volatile(
        "mma.sync.aligned.m16n8k16.row.col.f32.f16.f16.f32 "
        "{%0,%1,%2,%3}, {%4,%5,%6,%7}, {%8,%9}, {%0,%1,%2,%3};"
        : "+f"(c[0]), "+f"(c[1]), "+f"(c[2]), "+f"(c[3])
        : "r"(a0), "r"(a1), "r"(a2), "r"(a3), "r"(b0), "r"(b1));
}
__device__ __forceinline__ void ldsm4(uint32_t& r0, uint32_t& r1,
                                      uint32_t& r2, uint32_t& r3, uint32_t addr) {
    asm volatile("ldmatrix.sync.aligned.m8n8.x4.shared.b16 {%0,%1,%2,%3}, [%4];"
                 : "=r"(r0), "=r"(r1), "=r"(r2), "=r"(r3) : "r"(addr));
}
__device__ __forceinline__ void ldsm2(uint32_t& r0, uint32_t& r1, uint32_t addr) {
    asm volatile("ldmatrix.sync.aligned.m8n8.x2.shared.b16 {%0,%1}, [%2];"
                 : "=r"(r0), "=r"(r1) : "r"(addr));
}

// ---------------------------------------------------------------------------
// Degree / CSR build
// ---------------------------------------------------------------------------
__global__ void zero_deg_kernel() {
    int i = blockIdx.x * blockDim.x + threadIdx.x;
    if (i < BNN) g_degi[i] = 0;
}
__global__ void hist_kernel(const int* __restrict__ ei) {
    int i = blockIdx.x * blockDim.x + threadIdx.x;
    if (i >= BE) return;
    int b = i / E;
    int e = i - b * E;
    int dst = ei[b * 2 * E + E + e];
    atomicAdd(&g_degi[b * NN + dst], 1);
}
__global__ void dinv_kernel() {
    int i = blockIdx.x * blockDim.x + threadIdx.x;
    if (i < BNN) g_dinv[i] = rsqrtf(1.0f + (float)g_degi[i]);   // +1 self loop
}
// 3-phase exclusive scan of g_degi -> g_rowoff (+ cursor copy)
__global__ void scan1_kernel() {
    __shared__ int sh[256];
    int i = blockIdx.x * 256 + threadIdx.x;
    int v = (i < BNN) ? g_degi[i] : 0;
    sh[threadIdx.x] = v;
    __syncthreads();
    #pragma unroll
    for (int off = 1; off < 256; off <<= 1) {
        int t = (threadIdx.x >= off) ? sh[threadIdx.x - off] : 0;
        __syncthreads();
        sh[threadIdx.x] += t;
        __syncthreads();
    }
    if (i < BNN) g_rowoff[i] = sh[threadIdx.x] - v;
    if (threadIdx.x == 255) g_bsum[blockIdx.x] = sh[255];
}
__global__ void scan2_kernel() {
    __shared__ int sh[512];
    int t = threadIdx.x;
    int v = (t < NBLK) ? g_bsum[t] : 0;
    sh[t] = v;
    __syncthreads();
    #pragma unroll
    for (int off = 1; off < 512; off <<= 1) {
        int u = (t >= off) ? sh[t - off] : 0;
        __syncthreads();
        sh[t] += u;
        __syncthreads();
    }
    g_bsum[t] = sh[t] - v;   // exclusive
}
__global__ void scan3_kernel() {
    int i = blockIdx.x * blockDim.x + threadIdx.x;
    if (i >= BNN) return;
    int off = g_rowoff[i] + g_bsum[i >> 8];
    g_rowoff[i] = off;
    g_cursor[i] = off;
}
__global__ void fill_kernel(const int* __restrict__ ei) {
    int i = blockIdx.x * blockDim.x + threadIdx.x;
    if (i >= BE) return;
    int b = i / E;
    int e = i - b * E;
    const int* eb = ei + b * 2 * E;
    int gs = b * NN + eb[e];
    int gd = b * NN + eb[E + e];
    int pos = atomicAdd(&g_cursor[gd], 1);
    g_csr_src[pos]  = gs;
    g_csr_norm[pos] = g_dinv[gs] * g_dinv[gd];
}

// ---------------------------------------------------------------------------
// Weight / input conversion
// ---------------------------------------------------------------------------
__global__ void transpose_f16_kernel(const float* __restrict__ W, __half* __restrict__ Wt,
                                     int K, int N) {
    int i = blockIdx.x * blockDim.x + threadIdx.x;
    if (i >= K * N) return;
    int k = i / N, n = i % N;
    Wt[(size_t)n * K + k] = __float2half_rn(W[i]);
}
__global__ void cvt_f16_kernel(const float* __restrict__ in, __half* __restrict__ out, int n4) {
    int i = blockIdx.x * blockDim.x + threadIdx.x;
    if (i >= n4) return;
    float4 v = ((const float4*)in)[i];
    __half2 h01 = __floats2half2_rn(v.x, v.y);
    __half2 h23 = __floats2half2_rn(v.z, v.w);
    uint2 st;
    st.x = *(uint32_t*)&h01;
    st.y = *(uint32_t*)&h23;
    ((uint2*)out)[i] = st;
}

// ---------------------------------------------------------------------------
// FP16 GEMM, cp.async 3-stage pipeline + ldmatrix b16 fragments.
// EPI: 0 = plain fp16; 1 = leaky(C+bias) fp16; 3 = leaky(C+bias) fp32
// ---------------------------------------------------------------------------
constexpr int STAGE_BYTES = 16384;
constexpr int GEMM_SMEM   = 3 * STAGE_BYTES;

template <int EPI>
__global__ __launch_bounds__(256, 2)
void f16_gemm_kernel(const __half* __restrict__ At, const __half* __restrict__ Bt,
                     const float* __restrict__ bias, void* __restrict__ Cv,
                     int M, int Nn, int K) {
    extern __shared__ uint32_t sh[];

    const int tid  = threadIdx.x;
    const int lane = tid & 31;
    const int wid  = tid >> 5;
    const int wm   = wid & 1;
    const int wn   = wid >> 1;
    const int bx = blockIdx.x, by = blockIdx.y;

    const __half* Ablk = At + (size_t)by * 128 * K;
    const __half* Bblk = Bt + (size_t)bx * 128 * K;

    float acc[4][4][4];
    #pragma unroll
    for (int i = 0; i < 4; i++)
        #pragma unroll
        for (int j = 0; j < 4; j++)
            #pragma unroll
            for (int q = 0; q < 4; q++) acc[i][j][q] = 0.0f;

    const uint32_t sbase = (uint32_t)__cvta_generic_to_shared(sh);
    const int sRow = tid >> 1;
    const int sC2  = (tid & 1) * 2;

    auto issue = [&](int st, int kt) {
        uint32_t abase = sbase + st * STAGE_BYTES;
        uint32_t bbase = abase + 8192;
        #pragma unroll
        for (int q = 0; q < 2; q++) {
            int c = sC2 + q;
            uint32_t doff = sRow * 64 + ((c ^ ((sRow >> 1) & 3)) << 4);
            const __half* srcA = Ablk + (size_t)sRow * K + kt + c * 8;
            asm volatile("cp.async.cg.shared.global [%0], [%1], 16;"
                         :: "r"(abase + doff), "l"(srcA));
            const __half* srcB = Bblk + (size_t)sRow * K + kt + c * 8;
            asm volatile("cp.async.cg.shared.global [%0], [%1], 16;"
                         :: "r"(bbase + doff), "l"(srcB));
        }
    };
    auto compute = [&](int st) {
        uint32_t abase = sbase + st * STAGE_BYTES;
        uint32_t bbase = abase + 8192;
        #pragma unroll
        for (int s = 0; s < 2; s++) {
            uint32_t af[4][4];
            uint32_t bf[4][2];
            #pragma unroll
            for (int i = 0; i < 4; i++) {
                int row = wm * 64 + i * 16 + (lane & 7) + ((lane >> 3) & 1) * 8;
                int ch  = 2 * s + (lane >> 4);
                uint32_t addr = abase + row * 64 + ((ch ^ ((row >> 1) & 3)) << 4);
                ldsm4(af[i][0], af[i][1], af[i][2], af[i][3], addr);
            }
            #pragma unroll
            for (int j = 0; j < 4; j++) {
                int row = wn * 32 + j * 8 + (lane & 7);
                int ch  = 2 * s + ((lane >> 3) & 1);
                uint32_t addr = bbase + row * 64 + ((ch ^ ((row >> 1) & 3)) << 4);
                ldsm2(bf[j][0], bf[j][1], addr);
            }
            #pragma unroll
            for (int i = 0; i < 4; i++)
                #pragma unroll
                for (int j = 0; j < 4; j++)
                    mma_f16(acc[i][j], af[i][0], af[i][1], af[i][2], af[i][3],
                            bf[j][0], bf[j][1]);
        }
    };

    const int CH = K / 32;
    issue(0, 0);
    asm volatile("cp.async.commit_group;" ::: "memory");
    if (CH > 1) issue(1, 32);
    asm volatile("cp.async.commit_group;" ::: "memory");

    for (int c = 0; c < CH; c++) {
        asm volatile("cp.async.wait_group 1;" ::: "memory");
        __syncthreads();
        if (c + 2 < CH) issue((c + 2) % 3, (c + 2) * 32);
        asm volatile("cp.async.commit_group;" ::: "memory");
        compute(c % 3);
    }

    #pragma unroll
    for (int i = 0; i < 4; i++) {
        #pragma unroll
        for (int j = 0; j < 4; j++) {
            int col = wn * 32 + j * 8 + 2 * (lane & 3);
            float bx0 = 0.0f, bx1 = 0.0f;
            if (EPI != 0) { bx0 = bias[bx * 128 + col]; bx1 = bias[bx * 128 + col + 1]; }
            #pragma unroll
            for (int h = 0; h < 2; h++) {
                int row = wm * 64 + i * 16 + (lane >> 2) + h * 8;
                float vx = acc[i][j][h * 2 + 0] + bx0;
                float vy = acc[i][j][h * 2 + 1] + bx1;
                size_t idx = (size_t)(by * 128 + row) * Nn + bx * 128 + col;
                if (EPI != 0) {
                    vx = vx > 0.0f ? vx : NEG_SLOPE * vx;
                    vy = vy > 0.0f ? vy : NEG_SLOPE * vy;
                }
                if (EPI == 3) {
                    *(float2*)((float*)Cv + idx) = make_float2(vx, vy);
                } else {
                    __half2 hv = __floats2half2_rn(vx, vy);
                    *(uint32_t*)((__half*)Cv + idx) = *(uint32_t*)&hv;
                }
            }
        }
    }
}

// ---------------------------------------------------------------------------
// Gather-aggregate + fused post: one warp per dst row.
// acc = dinv^2 * xw[dst] + sum_nb norm * xw[src]; o1 = relu(acc+bc)+x0 -> fp16
// ---------------------------------------------------------------------------
__global__ __launch_bounds__(256)
void gather_kernel(const float* __restrict__ bc) {
    int w = (blockIdx.x * blockDim.x + threadIdx.x) >> 5;
    int lane = threadIdx.x & 31;
    if (w >= BNN) return;

    float dd = g_dinv[w];
    float selfs = dd * dd;
    const uint2* selfp = (const uint2*)(g_xwh + (size_t)w * F);
    uint2 sv = selfp[lane];
    float2 s01 = __half22float2(*(__half2*)&sv.x);
    float2 s23 = __half22float2(*(__half2*)&sv.y);
    float a0 = selfs * s01.x, a1 = selfs * s01.y;
    float a2 = selfs * s23.x, a3 = selfs * s23.y;

    int kbeg = g_rowoff[w];
    int kend = (w + 1 < BNN) ? g_rowoff[w + 1] : BE;
    for (int k = kbeg; k < kend; k++) {
        int gs = g_csr_src[k];          // lane-uniform (broadcast)
        float nm = g_csr_norm[k];
        uint2 v = ((const uint2*)(g_xwh + (size_t)gs * F))[lane];
        float2 f01 = __half22float2(*(__half2*)&v.x);
        float2 f23 = __half22float2(*(__half2*)&v.y);
        a0 = fmaf(nm, f01.x, a0);
        a1 = fmaf(nm, f01.y, a1);
        a2 = fmaf(nm, f23.x, a2);
        a3 = fmaf(nm, f23.y, a3);
    }

    float4 bb = ((const float4*)bc)[lane];
    uint2 xh = ((const uint2*)(g_x0h + (size_t)w * F))[lane];
    float2 x01 = __half22float2(*(__half2*)&xh.x);
    float2 x23 = __half22float2(*(__half2*)&xh.y);
    float o0 = fmaxf(a0 + bb.x, 0.0f) + x01.x;
    float o1 = fmaxf(a1 + bb.y, 0.0f) + x01.y;
    float o2 = fmaxf(a2 + bb.z, 0.0f) + x23.x;
    float o3 = fmaxf(a3 + bb.w, 0.0f) + x23.y;
    __half2 h01 = __floats2half2_rn(o0, o1);
    __half2 h23 = __floats2half2_rn(o2, o3);
    uint2 st;
    st.x = *(uint32_t*)&h01;
    st.y = *(uint32_t*)&h23;
    ((uint2*)(g_o1h + (size_t)w * F))[lane] = st;
}

// ---------------------------------------------------------------------------
extern "C" void kernel_launch(void* const* d_in, const int* in_sizes, int n_in,
                              void* d_out, int out_size) {
    const float* x0 = (const float*)d_in[0];       // [B,N,F]
    const int*   ei = (const int*)d_in[1];         // [B,2,E] int32
    const float* Wc = (const float*)d_in[2];       // [F,F]
    const float* bc = (const float*)d_in[3];       // [F]
    const float* W1 = (const float*)d_in[4];       // [F,H]
    const float* b1 = (const float*)d_in[5];       // [H]
    const float* W2 = (const float*)d_in[6];       // [H,H]
    const float* b2 = (const float*)d_in[7];       // [H]
    float* out = (float*)d_out;                    // [B,N,H]

    __half *xwh, *x0h, *o1h, *h1h, *wch, *w1h, *w2h;
    cudaGetSymbolAddress((void**)&xwh,  g_xwh);
    cudaGetSymbolAddress((void**)&x0h,  g_x0h);
    cudaGetSymbolAddress((void**)&o1h,  g_o1h);
    cudaGetSymbolAddress((void**)&h1h,  g_h1h);
    cudaGetSymbolAddress((void**)&wch,  g_wch);
    cudaGetSymbolAddress((void**)&w1h,  g_w1h);
    cudaGetSymbolAddress((void**)&w2h,  g_w2h);

    static bool attr_done = false;
    if (!attr_done) {
        cudaFuncSetAttribute(f16_gemm_kernel<0>, cudaFuncAttributeMaxDynamicSharedMemorySize, GEMM_SMEM);
        cudaFuncSetAttribute(f16_gemm_kernel<1>, cudaFuncAttributeMaxDynamicSharedMemorySize, GEMM_SMEM);
        cudaFuncSetAttribute(f16_gemm_kernel<3>, cudaFuncAttributeMaxDynamicSharedMemorySize, GEMM_SMEM);
        attr_done = true;
    }

    // 0) operand preparation (fp16)
    transpose_f16_kernel<<<(F * F + 255) / 256, 256>>>(Wc, wch, F, F);
    transpose_f16_kernel<<<(F * H + 255) / 256, 256>>>(W1, w1h, F, H);
    transpose_f16_kernel<<<(H * H + 255) / 256, 256>>>(W2, w2h, H, H);
    cvt_f16_kernel<<<(BNN * F / 4 + 255) / 256, 256>>>(x0, x0h, BNN * F / 4);

    // 1) degrees + CSR offsets
    zero_deg_kernel<<<NBLK, 256>>>();
    hist_kernel<<<(BE + 255) / 256, 256>>>(ei);
    dinv_kernel<<<NBLK, 256>>>();
    scan1_kernel<<<NBLK, 256>>>();
    scan2_kernel<<<1, 512>>>();
    scan3_kernel<<<NBLK, 256>>>();

    // 2) xw = x0 @ Wc -> fp16 xwh  (M=80000, N=128, K=128)
    {
        dim3 grid(1, BNN / 128);
        f16_gemm_kernel<0><<<grid, 256, GEMM_SMEM>>>(x0h, wch, nullptr, xwh, BNN, F, F);
    }

    // 3) CSR fill (src + precomputed norm)
    fill_kernel<<<(BE + 255) / 256, 256>>>(ei);

    // 4) gather-aggregate + fused post -> fp16 o1h
    gather_kernel<<<(BNN * 32 + 255) / 256, 256>>>(bc);

    // 5) h1 = leaky_relu(out1 @ W1 + b1) -> fp16  (N=256, K=128)
    {
        dim3 grid(H / 128, BNN / 128);
        f16_gemm_kernel<1><<<grid, 256, GEMM_SMEM>>>(o1h, w1h, b1, h1h, BNN, H, F);
    }

    // 6) out = leaky_relu(h1 @ W2 + b2) -> fp32  (N=256, K=256)
    {
        dim3 grid(H / 128, BNN / 128);
        f16_gemm_kernel<3><<<grid, 256, GEMM_SMEM>>>(h1h, w2h, b2, out, BNN, H, H);
    }
}

// round 14
// speedup vs baseline: 2.2998x; 1.0077x over previous
#include <cuda_runtime.h>
#include <cuda_fp16.h>
#include <cstdint>

// Problem constants (fixed by the dataset)
constexpr int B  = 8;
constexpr int NN = 10000;
constexpr int E  = 160000;
constexpr int F  = 128;   // GCN feature dim
constexpr int H  = 256;   // hidden dim
constexpr int BNN = B * NN;          // 80000 rows
constexpr int BE  = B * E;           // 1.28M edges
constexpr int NBLK = (BNN + 255) / 256;   // 313 scan blocks
constexpr float NEG_SLOPE = 0.01f;

// Scratch (allocation-free: __device__ globals)
__device__ float  g_dinv[BNN];
__device__ int    g_degi[BNN];
__device__ int    g_rowoff[BNN];
__device__ int    g_cursor[BNN];
__device__ int    g_bsum[512];
__device__ int    g_csr_src[BE];
__device__ float  g_csr_norm[BE];
__device__ __half g_xwh[(size_t)BNN * F];     // fp16 xw (gather source)
__device__ __half g_x0h[(size_t)BNN * F];     // fp16 x0
__device__ __half g_o1h[(size_t)BNN * F];     // fp16 out1
__device__ __half g_wch[F * F];               // Wc^T fp16 [N][K]
__device__ __half g_w1h[H * F];               // W1^T fp16 [N][K]
__device__ __half g_w2h[H * H];               // W2^T fp16 [N][K]

__device__ __forceinline__ void mma_f16(float c[4], uint32_t a0, uint32_t a1,
                                        uint32_t a2, uint32_t a3,
                                        uint32_t b0, uint32_t b1) {
    asm volatile(
        "mma.sync.aligned.m16n8k16.row.col.f32.f16.f16.f32 "
        "{%0,%1,%2,%3}, {%4,%5,%6,%7}, {%8,%9}, {%0,%1,%2,%3};"
        : "+f"(c[0]), "+f"(c[1]), "+f"(c[2]), "+f"(c[3])
        : "r"(a0), "r"(a1), "r"(a2), "r"(a3), "r"(b0), "r"(b1));
}
__device__ __forceinline__ void ldsm4(uint32_t& r0, uint32_t& r1,
                                      uint32_t& r2, uint32_t& r3, uint32_t addr) {
    asm volatile("ldmatrix.sync.aligned.m8n8.x4.shared.b16 {%0,%1,%2,%3}, [%4];"
                 : "=r"(r0), "=r"(r1), "=r"(r2), "=r"(r3) : "r"(addr));
}
__device__ __forceinline__ void ldsm2(uint32_t& r0, uint32_t& r1, uint32_t addr) {
    asm volatile("ldmatrix.sync.aligned.m8n8.x2.shared.b16 {%0,%1}, [%2];"
                 : "=r"(r0), "=r"(r1) : "r"(addr));
}

// ---------------------------------------------------------------------------
// Degree / CSR build
// ---------------------------------------------------------------------------
__global__ void zero_deg_kernel() {
    int i = blockIdx.x * blockDim.x + threadIdx.x;
    if (i < BNN) g_degi[i] = 0;
}
__global__ void hist_kernel(const int* __restrict__ ei) {
    int i = blockIdx.x * blockDim.x + threadIdx.x;
    if (i >= BE) return;
    int b = i / E;
    int e = i - b * E;
    int dst = ei[b * 2 * E + E + e];
    atomicAdd(&g_degi[b * NN + dst], 1);
}
__global__ void dinv_kernel() {
    int i = blockIdx.x * blockDim.x + threadIdx.x;
    if (i < BNN) g_dinv[i] = rsqrtf(1.0f + (float)g_degi[i]);   // +1 self loop
}
__global__ void scan1_kernel() {
    __shared__ int sh[256];
    int i = blockIdx.x * 256 + threadIdx.x;
    int v = (i < BNN) ? g_degi[i] : 0;
    sh[threadIdx.x] = v;
    __syncthreads();
    #pragma unroll
    for (int off = 1; off < 256; off <<= 1) {
        int t = (threadIdx.x >= off) ? sh[threadIdx.x - off] : 0;
        __syncthreads();
        sh[threadIdx.x] += t;
        __syncthreads();
    }
    if (i < BNN) g_rowoff[i] = sh[threadIdx.x] - v;
    if (threadIdx.x == 255) g_bsum[blockIdx.x] = sh[255];
}
__global__ void scan2_kernel() {
    __shared__ int sh[512];
    int t = threadIdx.x;
    int v = (t < NBLK) ? g_bsum[t] : 0;
    sh[t] = v;
    __syncthreads();
    #pragma unroll
    for (int off = 1; off < 512; off <<= 1) {
        int u = (t >= off) ? sh[t - off] : 0;
        __syncthreads();
        sh[t] += u;
        __syncthreads();
    }
    g_bsum[t] = sh[t] - v;   // exclusive
}
__global__ void scan3_kernel() {
    int i = blockIdx.x * blockDim.x + threadIdx.x;
    if (i >= BNN) return;
    int off = g_rowoff[i] + g_bsum[i >> 8];
    g_rowoff[i] = off;
    g_cursor[i] = off;
}
__global__ void fill_kernel(const int* __restrict__ ei) {
    int i = blockIdx.x * blockDim.x + threadIdx.x;
    if (i >= BE) return;
    int b = i / E;
    int e = i - b * E;
    const int* eb = ei + b * 2 * E;
    int gs = b * NN + eb[e];
    int gd = b * NN + eb[E + e];
    int pos = atomicAdd(&g_cursor[gd], 1);
    g_csr_src[pos]  = gs;
    g_csr_norm[pos] = g_dinv[gs] * g_dinv[gd];
}

// ---------------------------------------------------------------------------
// Weight / input conversion
// ---------------------------------------------------------------------------
__global__ void transpose_f16_kernel(const float* __restrict__ W, __half* __restrict__ Wt,
                                     int K, int N) {
    int i = blockIdx.x * blockDim.x + threadIdx.x;
    if (i >= K * N) return;
    int k = i / N, n = i % N;
    Wt[(size_t)n * K + k] = __float2half_rn(W[i]);
}
__global__ void cvt_f16_kernel(const float* __restrict__ in, __half* __restrict__ out, int n4) {
    int i = blockIdx.x * blockDim.x + threadIdx.x;
    if (i >= n4) return;
    float4 v = ((const float4*)in)[i];
    __half2 h01 = __floats2half2_rn(v.x, v.y);
    __half2 h23 = __floats2half2_rn(v.z, v.w);
    uint2 st;
    st.x = *(uint32_t*)&h01;
    st.y = *(uint32_t*)&h23;
    ((uint2*)out)[i] = st;
}

// ---------------------------------------------------------------------------
// FP16 GEMM (single layer): cp.async 3-stage + ldmatrix. EPI0 = plain fp16 out.
// ---------------------------------------------------------------------------
constexpr int STAGE_BYTES = 16384;
constexpr int GEMM_SMEM   = 3 * STAGE_BYTES;

__global__ __launch_bounds__(256, 2)
void f16_gemm_kernel(const __half* __restrict__ At, const __half* __restrict__ Bt,
                     __half* __restrict__ Ch, int M, int Nn, int K) {
    extern __shared__ uint32_t sh[];

    const int tid  = threadIdx.x;
    const int lane = tid & 31;
    const int wid  = tid >> 5;
    const int wm   = wid & 1;
    const int wn   = wid >> 1;
    const int bx = blockIdx.x, by = blockIdx.y;

    const __half* Ablk = At + (size_t)by * 128 * K;
    const __half* Bblk = Bt + (size_t)bx * 128 * K;

    float acc[4][4][4];
    #pragma unroll
    for (int i = 0; i < 4; i++)
        #pragma unroll
        for (int j = 0; j < 4; j++)
            #pragma unroll
            for (int q = 0; q < 4; q++) acc[i][j][q] = 0.0f;

    const uint32_t sbase = (uint32_t)__cvta_generic_to_shared(sh);
    const int sRow = tid >> 1;
    const int sC2  = (tid & 1) * 2;

    auto issue = [&](int st, int kt) {
        uint32_t abase = sbase + st * STAGE_BYTES;
        uint32_t bbase = abase + 8192;
        #pragma unroll
        for (int q = 0; q < 2; q++) {
            int c = sC2 + q;
            uint32_t doff = sRow * 64 + ((c ^ ((sRow >> 1) & 3)) << 4);
            asm volatile("cp.async.cg.shared.global [%0], [%1], 16;"
                         :: "r"(abase + doff), "l"(Ablk + (size_t)sRow * K + kt + c * 8));
            asm volatile("cp.async.cg.shared.global [%0], [%1], 16;"
                         :: "r"(bbase + doff), "l"(Bblk + (size_t)sRow * K + kt + c * 8));
        }
    };
    auto compute = [&](int st) {
        uint32_t abase = sbase + st * STAGE_BYTES;
        uint32_t bbase = abase + 8192;
        #pragma unroll
        for (int s = 0; s < 2; s++) {
            uint32_t af[4][4];
            uint32_t bf[4][2];
            #pragma unroll
            for (int i = 0; i < 4; i++) {
                int row = wm * 64 + i * 16 + (lane & 7) + ((lane >> 3) & 1) * 8;
                int ch  = 2 * s + (lane >> 4);
                ldsm4(af[i][0], af[i][1], af[i][2], af[i][3],
                      abase + row * 64 + ((ch ^ ((row >> 1) & 3)) << 4));
            }
            #pragma unroll
            for (int j = 0; j < 4; j++) {
                int row = wn * 32 + j * 8 + (lane & 7);
                int ch  = 2 * s + ((lane >> 3) & 1);
                ldsm2(bf[j][0], bf[j][1],
                      bbase + row * 64 + ((ch ^ ((row >> 1) & 3)) << 4));
            }
            #pragma unroll
            for (int i = 0; i < 4; i++)
                #pragma unroll
                for (int j = 0; j < 4; j++)
                    mma_f16(acc[i][j], af[i][0], af[i][1], af[i][2], af[i][3],
                            bf[j][0], bf[j][1]);
        }
    };

    const int CH = K / 32;
    issue(0, 0);
    asm volatile("cp.async.commit_group;" ::: "memory");
    issue(1, 32);
    asm volatile("cp.async.commit_group;" ::: "memory");
    for (int c = 0; c < CH; c++) {
        asm volatile("cp.async.wait_group 1;" ::: "memory");
        __syncthreads();
        if (c + 2 < CH) issue((c + 2) % 3, (c + 2) * 32);
        asm volatile("cp.async.commit_group;" ::: "memory");
        compute(c % 3);
    }

    #pragma unroll
    for (int i = 0; i < 4; i++)
        #pragma unroll
        for (int j = 0; j < 4; j++) {
            int col = wn * 32 + j * 8 + 2 * (lane & 3);
            #pragma unroll
            for (int h = 0; h < 2; h++) {
                int row = wm * 64 + i * 16 + (lane >> 2) + h * 8;
                __half2 hv = __floats2half2_rn(acc[i][j][h * 2], acc[i][j][h * 2 + 1]);
                *(uint32_t*)(Ch + (size_t)(by * 128 + row) * Nn + bx * 128 + col) = *(uint32_t*)&hv;
            }
        }
}

// ---------------------------------------------------------------------------
// Fused GEMM2+GEMM3: out = leaky(leaky(o1@W1+b1)@W2+b2), h1 kept in smem.
// smem: h1buf 64KB (128 rows x 512B, swizzle chunk^(row&7)) + 48KB stages.
// ---------------------------------------------------------------------------
constexpr int H1_BYTES   = 128 * 512;                 // 65536
constexpr int F23_SMEM   = H1_BYTES + GEMM_SMEM;      // 114688

__global__ __launch_bounds__(256)
void fused23_kernel(const __half* __restrict__ o1h, const __half* __restrict__ w1h,
                    const __half* __restrict__ w2h, const float* __restrict__ b1,
                    const float* __restrict__ b2, float* __restrict__ out) {
    extern __shared__ uint32_t sh[];

    const int tid  = threadIdx.x;
    const int lane = tid & 31;
    const int wid  = tid >> 5;
    const int wm   = wid & 1;
    const int wn   = wid >> 1;
    const int by = blockIdx.x;

    const uint32_t sbase  = (uint32_t)__cvta_generic_to_shared(sh);
    const uint32_t h1base = sbase;
    const uint32_t stbase = sbase + H1_BYTES;
    const int sRow = tid >> 1;
    const int sC2  = (tid & 1) * 2;

    float acc[4][4][4];

    const __half* Ablk = o1h + (size_t)by * 128 * F;

    // ---------------- Phase 1: h1 = leaky(o1 @ W1 + b1) -> smem ----------------
    #pragma unroll 1
    for (int half = 0; half < 2; half++) {
        #pragma unroll
        for (int i = 0; i < 4; i++)
            #pragma unroll
            for (int j = 0; j < 4; j++)
                #pragma unroll
                for (int q = 0; q < 4; q++) acc[i][j][q] = 0.0f;

        const __half* Bblk = w1h + (size_t)half * 128 * F;

        auto issue1 = [&](int st, int kt) {
            uint32_t abase = stbase + st * STAGE_BYTES;
            uint32_t bbase = abase + 8192;
            #pragma unroll
            for (int q = 0; q < 2; q++) {
                int c = sC2 + q;
                uint32_t doff = sRow * 64 + ((c ^ ((sRow >> 1) & 3)) << 4);
                asm volatile("cp.async.cg.shared.global [%0], [%1], 16;"
                             :: "r"(abase + doff), "l"(Ablk + (size_t)sRow * F + kt + c * 8));
                asm volatile("cp.async.cg.shared.global [%0], [%1], 16;"
                             :: "r"(bbase + doff), "l"(Bblk + (size_t)sRow * F + kt + c * 8));
            }
        };
        auto compute1 = [&](int st) {
            uint32_t abase = stbase + st * STAGE_BYTES;
            uint32_t bbase = abase + 8192;
            #pragma unroll
            for (int s = 0; s < 2; s++) {
                uint32_t af[4][4], bf[4][2];
                #pragma unroll
                for (int i = 0; i < 4; i++) {
                    int row = wm * 64 + i * 16 + (lane & 7) + ((lane >> 3) & 1) * 8;
                    int ch  = 2 * s + (lane >> 4);
                    ldsm4(af[i][0], af[i][1], af[i][2], af[i][3],
                          abase + row * 64 + ((ch ^ ((row >> 1) & 3)) << 4));
                }
                #pragma unroll
                for (int j = 0; j < 4; j++) {
                    int row = wn * 32 + j * 8 + (lane & 7);
                    int ch  = 2 * s + ((lane >> 3) & 1);
                    ldsm2(bf[j][0], bf[j][1],
                          bbase + row * 64 + ((ch ^ ((row >> 1) & 3)) << 4));
                }
                #pragma unroll
                for (int i = 0; i < 4; i++)
                    #pragma unroll
                    for (int j = 0; j < 4; j++)
                        mma_f16(acc[i][j], af[i][0], af[i][1], af[i][2], af[i][3],
                                bf[j][0], bf[j][1]);
            }
        };

        issue1(0, 0);
        asm volatile("cp.async.commit_group;" ::: "memory");
        issue1(1, 32);
        asm volatile("cp.async.commit_group;" ::: "memory");
        for (int c = 0; c < 4; c++) {
            asm volatile("cp.async.wait_group 1;" ::: "memory");
            __syncthreads();
            if (c + 2 < 4) issue1((c + 2) % 3, (c + 2) * 32);
            asm volatile("cp.async.commit_group;" ::: "memory");
            compute1(c % 3);
        }
        __syncthreads();   // stages fully consumed before reuse / h1 writes ordered

        // epilogue -> smem h1buf (fp16, swizzle ch ^ (row&7) on 512B rows)
        #pragma unroll
        for (int i = 0; i < 4; i++)
            #pragma unroll
            for (int j = 0; j < 4; j++) {
                int gcol = half * 128 + wn * 32 + j * 8 + 2 * (lane & 3);
                int ch16 = gcol >> 3;
                float bx0 = b1[gcol], bx1 = b1[gcol + 1];
                #pragma unroll
                for (int h = 0; h < 2; h++) {
                    int row = wm * 64 + i * 16 + (lane >> 2) + h * 8;
                    float vx = acc[i][j][h * 2] + bx0;
                    float vy = acc[i][j][h * 2 + 1] + bx1;
                    vx = vx > 0.0f ? vx : NEG_SLOPE * vx;
                    vy = vy > 0.0f ? vy : NEG_SLOPE * vy;
                    __half2 hv = __floats2half2_rn(vx, vy);
                    uint32_t addr = h1base + row * 512 + ((ch16 ^ (row & 7)) << 4)
                                  + (gcol & 7) * 2;
                    asm volatile("st.shared.b32 [%0], %1;" :: "r"(addr), "r"(*(uint32_t*)&hv));
                }
            }
        __syncthreads();
    }

    // ---------------- Phase 2: out = leaky(h1 @ W2 + b2) ----------------
    #pragma unroll 1
    for (int outhalf = 0; outhalf < 2; outhalf++) {
        #pragma unroll
        for (int i = 0; i < 4; i++)
            #pragma unroll
            for (int j = 0; j < 4; j++)
                #pragma unroll
                for (int q = 0; q < 4; q++) acc[i][j][q] = 0.0f;

        const __half* Bblk = w2h + (size_t)outhalf * 128 * H;

        auto issue2 = [&](int st, int kt) {
            uint32_t bbase = stbase + st * STAGE_BYTES;   // B-only stage (8KB used)
            #pragma unroll
            for (int q = 0; q < 2; q++) {
                int c = sC2 + q;
                uint32_t doff = sRow * 64 + ((c ^ ((sRow >> 1) & 3)) << 4);
                asm volatile("cp.async.cg.shared.global [%0], [%1], 16;"
                             :: "r"(bbase + doff), "l"(Bblk + (size_t)sRow * H + kt + c * 8));
            }
        };
        auto compute2 = [&](int st, int kc) {
            uint32_t bbase = stbase + st * STAGE_BYTES;
            #pragma unroll
            for (int s = 0; s < 2; s++) {
                uint32_t af[4][4], bf[4][2];
                #pragma unroll
                for (int i = 0; i < 4; i++) {
                    int row = wm * 64 + i * 16 + (lane & 7) + ((lane >> 3) & 1) * 8;
                    int ch  = kc * 4 + 2 * s + (lane >> 4);
                    ldsm4(af[i][0], af[i][1], af[i][2], af[i][3],
                          h1base + row * 512 + ((ch ^ (row & 7)) << 4));
                }
                #pragma unroll
                for (int j = 0; j < 4; j++) {
                    int row = wn * 32 + j * 8 + (lane & 7);
                    int ch  = 2 * s + ((lane >> 3) & 1);
                    ldsm2(bf[j][0], bf[j][1],
                          bbase + row * 64 + ((ch ^ ((row >> 1) & 3)) << 4));
                }
                #pragma unroll
                for (int i = 0; i < 4; i++)
                    #pragma unroll
                    for (int j = 0; j < 4; j++)
                        mma_f16(acc[i][j], af[i][0], af[i][1], af[i][2], af[i][3],
                                bf[j][0], bf[j][1]);
            }
        };

        issue2(0, 0);
        asm volatile("cp.async.commit_group;" ::: "memory");
        issue2(1, 32);
        asm volatile("cp.async.commit_group;" ::: "memory");
        for (int c = 0; c < 8; c++) {
            asm volatile("cp.async.wait_group 1;" ::: "memory");
            __syncthreads();
            if (c + 2 < 8) issue2((c + 2) % 3, (c + 2) * 32);
            asm volatile("cp.async.commit_group;" ::: "memory");
            compute2(c % 3, c);
        }
        __syncthreads();

        #pragma unroll
        for (int i = 0; i < 4; i++)
            #pragma unroll
            for (int j = 0; j < 4; j++) {
                int gcol = outhalf * 128 + wn * 32 + j * 8 + 2 * (lane & 3);
                float bx0 = b2[gcol], bx1 = b2[gcol + 1];
                #pragma unroll
                for (int h = 0; h < 2; h++) {
                    int row = wm * 64 + i * 16 + (lane >> 2) + h * 8;
                    float vx = acc[i][j][h * 2] + bx0;
                    float vy = acc[i][j][h * 2 + 1] + bx1;
                    vx = vx > 0.0f ? vx : NEG_SLOPE * vx;
                    vy = vy > 0.0f ? vy : NEG_SLOPE * vy;
                    *(float2*)(out + (size_t)(by * 128 + row) * H + gcol) = make_float2(vx, vy);
                }
            }
    }
}

// ---------------------------------------------------------------------------
// Gather-aggregate + fused post: one warp per dst row.
// ---------------------------------------------------------------------------
__global__ __launch_bounds__(256)
void gather_kernel(const float* __restrict__ bc) {
    int w = (blockIdx.x * blockDim.x + threadIdx.x) >> 5;
    int lane = threadIdx.x & 31;
    if (w >= BNN) return;

    float dd = g_dinv[w];
    float selfs = dd * dd;
    uint2 sv = ((const uint2*)(g_xwh + (size_t)w * F))[lane];
    float2 s01 = __half22float2(*(__half2*)&sv.x);
    float2 s23 = __half22float2(*(__half2*)&sv.y);
    float a0 = selfs * s01.x, a1 = selfs * s01.y;
    float a2 = selfs * s23.x, a3 = selfs * s23.y;

    int kbeg = g_rowoff[w];
    int kend = (w + 1 < BNN) ? g_rowoff[w + 1] : BE;
    for (int k = kbeg; k < kend; k++) {
        int gs = g_csr_src[k];
        float nm = g_csr_norm[k];
        uint2 v = ((const uint2*)(g_xwh + (size_t)gs * F))[lane];
        float2 f01 = __half22float2(*(__half2*)&v.x);
        float2 f23 = __half22float2(*(__half2*)&v.y);
        a0 = fmaf(nm, f01.x, a0);
        a1 = fmaf(nm, f01.y, a1);
        a2 = fmaf(nm, f23.x, a2);
        a3 = fmaf(nm, f23.y, a3);
    }

    float4 bb = ((const float4*)bc)[lane];
    uint2 xh = ((const uint2*)(g_x0h + (size_t)w * F))[lane];
    float2 x01 = __half22float2(*(__half2*)&xh.x);
    float2 x23 = __half22float2(*(__half2*)&xh.y);
    float o0 = fmaxf(a0 + bb.x, 0.0f) + x01.x;
    float o1 = fmaxf(a1 + bb.y, 0.0f) + x01.y;
    float o2 = fmaxf(a2 + bb.z, 0.0f) + x23.x;
    float o3 = fmaxf(a3 + bb.w, 0.0f) + x23.y;
    __half2 h01 = __floats2half2_rn(o0, o1);
    __half2 h23 = __floats2half2_rn(o2, o3);
    uint2 st;
    st.x = *(uint32_t*)&h01;
    st.y = *(uint32_t*)&h23;
    ((uint2*)(g_o1h + (size_t)w * F))[lane] = st;
}

// ---------------------------------------------------------------------------
extern "C" void kernel_launch(void* const* d_in, const int* in_sizes, int n_in,
                              void* d_out, int out_size) {
    const float* x0 = (const float*)d_in[0];       // [B,N,F]
    const int*   ei = (const int*)d_in[1];         // [B,2,E] int32
    const float* Wc = (const float*)d_in[2];       // [F,F]
    const float* bc = (const float*)d_in[3];       // [F]
    const float* W1 = (const float*)d_in[4];       // [F,H]
    const float* b1 = (const float*)d_in[5];       // [H]
    const float* W2 = (const float*)d_in[6];       // [H,H]
    const float* b2 = (const float*)d_in[7];       // [H]
    float* out = (float*)d_out;                    // [B,N,H]

    __half *xwh, *x0h, *o1h, *wch, *w1h, *w2h;
    cudaGetSymbolAddress((void**)&xwh,  g_xwh);
    cudaGetSymbolAddress((void**)&x0h,  g_x0h);
    cudaGetSymbolAddress((void**)&o1h,  g_o1h);
    cudaGetSymbolAddress((void**)&wch,  g_wch);
    cudaGetSymbolAddress((void**)&w1h,  g_w1h);
    cudaGetSymbolAddress((void**)&w2h,  g_w2h);

    static bool attr_done = false;
    if (!attr_done) {
        cudaFuncSetAttribute(f16_gemm_kernel, cudaFuncAttributeMaxDynamicSharedMemorySize, GEMM_SMEM);
        cudaFuncSetAttribute(fused23_kernel, cudaFuncAttributeMaxDynamicSharedMemorySize, F23_SMEM);
        attr_done = true;
    }

    // 0) operand preparation (fp16)
    transpose_f16_kernel<<<(F * F + 255) / 256, 256>>>(Wc, wch, F, F);
    transpose_f16_kernel<<<(F * H + 255) / 256, 256>>>(W1, w1h, F, H);
    transpose_f16_kernel<<<(H * H + 255) / 256, 256>>>(W2, w2h, H, H);
    cvt_f16_kernel<<<(BNN * F / 4 + 255) / 256, 256>>>(x0, x0h, BNN * F / 4);

    // 1) degrees + CSR offsets
    zero_deg_kernel<<<NBLK, 256>>>();
    hist_kernel<<<(BE + 255) / 256, 256>>>(ei);
    dinv_kernel<<<NBLK, 256>>>();
    scan1_kernel<<<NBLK, 256>>>();
    scan2_kernel<<<1, 512>>>();
    scan3_kernel<<<NBLK, 256>>>();

    // 2) xw = x0 @ Wc -> fp16 xwh  (M=80000, N=128, K=128)
    {
        dim3 grid(1, BNN / 128);
        f16_gemm_kernel<<<grid, 256, GEMM_SMEM>>>(x0h, wch, xwh, BNN, F, F);
    }

    // 3) CSR fill (src + precomputed norm)
    fill_kernel<<<(BE + 255) / 256, 256>>>(ei);

    // 4) gather-aggregate + fused post -> fp16 o1h
    gather_kernel<<<(BNN * 32 + 255) / 256, 256>>>(bc);

    // 5+6) fused: out = leaky(leaky(o1@W1+b1)@W2+b2)
    fused23_kernel<<<BNN / 128, 256, F23_SMEM>>>(o1h, w1h, w2h, b1, b2, out);
}

// round 15
// speedup vs baseline: 2.5858x; 1.1243x over previous
#include <cuda_runtime.h>
#include <cuda_fp16.h>
#include <cstdint>

// Problem constants (fixed by the dataset)
constexpr int B  = 8;
constexpr int NN = 10000;
constexpr int E  = 160000;
constexpr int F  = 128;   // GCN feature dim
constexpr int H  = 256;   // hidden dim
constexpr int BNN = B * NN;          // 80000 rows
constexpr int BE  = B * E;           // 1.28M edges
constexpr int NBLK = (BNN + 255) / 256;   // 313 scan blocks
constexpr float NEG_SLOPE = 0.01f;

// Scratch (allocation-free: __device__ globals)
__device__ float  g_dinv[BNN];
__device__ int    g_degi[BNN];
__device__ int    g_rowoff[BNN];
__device__ int    g_cursor[BNN];
__device__ int    g_bsum[512];
__device__ int    g_csr_src[BE];
__device__ float  g_csr_norm[BE];
__device__ __half g_xwh[(size_t)BNN * F];     // fp16 xw (gather source)
__device__ __half g_x0h[(size_t)BNN * F];     // fp16 x0
__device__ __half g_o1h[(size_t)BNN * F];     // fp16 out1
__device__ __half g_wch[F * F];               // Wc^T fp16 [N][K]
__device__ __half g_w1h[H * F];               // W1^T fp16 [N][K]
__device__ __half g_w2h[H * H];               // W2^T fp16 [N][K]

__device__ __forceinline__ void mma_f16(float c[4], uint32_t a0, uint32_t a1,
                                        uint32_t a2, uint32_t a3,
                                        uint32_t b0, uint32_t b1) {
    asm volatile(
        "mma.sync.aligned.m16n8k16.row.col.f32.f16.f16.f32 "
        "{%0,%1,%2,%3}, {%4,%5,%6,%7}, {%8,%9}, {%0,%1,%2,%3};"
        : "+f"(c[0]), "+f"(c[1]), "+f"(c[2]), "+f"(c[3])
        : "r"(a0), "r"(a1), "r"(a2), "r"(a3), "r"(b0), "r"(b1));
}
__device__ __forceinline__ void ldsm4(uint32_t& r0, uint32_t& r1,
                                      uint32_t& r2, uint32_t& r3, uint32_t addr) {
    asm volatile("ldmatrix.sync.aligned.m8n8.x4.shared.b16 {%0,%1,%2,%3}, [%4];"
                 : "=r"(r0), "=r"(r1), "=r"(r2), "=r"(r3) : "r"(addr));
}
__device__ __forceinline__ void ldsm2(uint32_t& r0, uint32_t& r1, uint32_t addr) {
    asm volatile("ldmatrix.sync.aligned.m8n8.x2.shared.b16 {%0,%1}, [%2];"
                 : "=r"(r0), "=r"(r1) : "r"(addr));
}

// ---------------------------------------------------------------------------
// Degree / CSR build
// ---------------------------------------------------------------------------
__global__ void zero_deg_kernel() {
    int i = blockIdx.x * blockDim.x + threadIdx.x;
    if (i < BNN) g_degi[i] = 0;
}
__global__ void hist_kernel(const int* __restrict__ ei) {
    int i = blockIdx.x * blockDim.x + threadIdx.x;
    if (i >= BE) return;
    int b = i / E;
    int e = i - b * E;
    int dst = ei[b * 2 * E + E + e];
    atomicAdd(&g_degi[b * NN + dst], 1);
}
__global__ void dinv_kernel() {
    int i = blockIdx.x * blockDim.x + threadIdx.x;
    if (i < BNN) g_dinv[i] = rsqrtf(1.0f + (float)g_degi[i]);   // +1 self loop
}
__global__ void scan1_kernel() {
    __shared__ int sh[256];
    int i = blockIdx.x * 256 + threadIdx.x;
    int v = (i < BNN) ? g_degi[i] : 0;
    sh[threadIdx.x] = v;
    __syncthreads();
    #pragma unroll
    for (int off = 1; off < 256; off <<= 1) {
        int t = (threadIdx.x >= off) ? sh[threadIdx.x - off] : 0;
        __syncthreads();
        sh[threadIdx.x] += t;
        __syncthreads();
    }
    if (i < BNN) g_rowoff[i] = sh[threadIdx.x] - v;
    if (threadIdx.x == 255) g_bsum[blockIdx.x] = sh[255];
}
__global__ void scan2_kernel() {
    __shared__ int sh[512];
    int t = threadIdx.x;
    int v = (t < NBLK) ? g_bsum[t] : 0;
    sh[t] = v;
    __syncthreads();
    #pragma unroll
    for (int off = 1; off < 512; off <<= 1) {
        int u = (t >= off) ? sh[t - off] : 0;
        __syncthreads();
        sh[t] += u;
        __syncthreads();
    }
    g_bsum[t] = sh[t] - v;   // exclusive
}
__global__ void scan3_kernel() {
    int i = blockIdx.x * blockDim.x + threadIdx.x;
    if (i >= BNN) return;
    int off = g_rowoff[i] + g_bsum[i >> 8];
    g_rowoff[i] = off;
    g_cursor[i] = off;
}
__global__ void fill_kernel(const int* __restrict__ ei) {
    int i = blockIdx.x * blockDim.x + threadIdx.x;
    if (i >= BE) return;
    int b = i / E;
    int e = i - b * E;
    const int* eb = ei + b * 2 * E;
    int gs = b * NN + eb[e];
    int gd = b * NN + eb[E + e];
    int pos = atomicAdd(&g_cursor[gd], 1);
    g_csr_src[pos]  = gs;
    g_csr_norm[pos] = g_dinv[gs] * g_dinv[gd];
}

// ---------------------------------------------------------------------------
// Weight / input conversion
// ---------------------------------------------------------------------------
__global__ void transpose_f16_kernel(const float* __restrict__ W, __half* __restrict__ Wt,
                                     int K, int N) {
    int i = blockIdx.x * blockDim.x + threadIdx.x;
    if (i >= K * N) return;
    int k = i / N, n = i % N;
    Wt[(size_t)n * K + k] = __float2half_rn(W[i]);
}
__global__ void cvt_f16_kernel(const float* __restrict__ in, __half* __restrict__ out, int n4) {
    int i = blockIdx.x * blockDim.x + threadIdx.x;
    if (i >= n4) return;
    float4 v = ((const float4*)in)[i];
    __half2 h01 = __floats2half2_rn(v.x, v.y);
    __half2 h23 = __floats2half2_rn(v.z, v.w);
    uint2 st;
    st.x = *(uint32_t*)&h01;
    st.y = *(uint32_t*)&h23;
    ((uint2*)out)[i] = st;
}

// ---------------------------------------------------------------------------
// FP16 GEMM (single layer): cp.async 3-stage + ldmatrix, plain fp16 out.
// ---------------------------------------------------------------------------
constexpr int STAGE_BYTES = 16384;
constexpr int GEMM_SMEM   = 3 * STAGE_BYTES;

__global__ __launch_bounds__(256, 2)
void f16_gemm_kernel(const __half* __restrict__ At, const __half* __restrict__ Bt,
                     __half* __restrict__ Ch, int M, int Nn, int K) {
    extern __shared__ uint32_t sh[];

    const int tid  = threadIdx.x;
    const int lane = tid & 31;
    const int wid  = tid >> 5;
    const int wm   = wid & 1;
    const int wn   = wid >> 1;
    const int bx = blockIdx.x, by = blockIdx.y;

    const __half* Ablk = At + (size_t)by * 128 * K;
    const __half* Bblk = Bt + (size_t)bx * 128 * K;

    float acc[4][4][4];
    #pragma unroll
    for (int i = 0; i < 4; i++)
        #pragma unroll
        for (int j = 0; j < 4; j++)
            #pragma unroll
            for (int q = 0; q < 4; q++) acc[i][j][q] = 0.0f;

    const uint32_t sbase = (uint32_t)__cvta_generic_to_shared(sh);
    const int sRow = tid >> 1;
    const int sC2  = (tid & 1) * 2;

    auto issue = [&](int st, int kt) {
        uint32_t abase = sbase + st * STAGE_BYTES;
        uint32_t bbase = abase + 8192;
        #pragma unroll
        for (int q = 0; q < 2; q++) {
            int c = sC2 + q;
            uint32_t doff = sRow * 64 + ((c ^ ((sRow >> 1) & 3)) << 4);
            asm volatile("cp.async.cg.shared.global [%0], [%1], 16;"
                         :: "r"(abase + doff), "l"(Ablk + (size_t)sRow * K + kt + c * 8));
            asm volatile("cp.async.cg.shared.global [%0], [%1], 16;"
                         :: "r"(bbase + doff), "l"(Bblk + (size_t)sRow * K + kt + c * 8));
        }
    };
    auto compute = [&](int st) {
        uint32_t abase = sbase + st * STAGE_BYTES;
        uint32_t bbase = abase + 8192;
        #pragma unroll
        for (int s = 0; s < 2; s++) {
            uint32_t af[4][4];
            uint32_t bf[4][2];
            #pragma unroll
            for (int i = 0; i < 4; i++) {
                int row = wm * 64 + i * 16 + (lane & 7) + ((lane >> 3) & 1) * 8;
                int ch  = 2 * s + (lane >> 4);
                ldsm4(af[i][0], af[i][1], af[i][2], af[i][3],
                      abase + row * 64 + ((ch ^ ((row >> 1) & 3)) << 4));
            }
            #pragma unroll
            for (int j = 0; j < 4; j++) {
                int row = wn * 32 + j * 8 + (lane & 7);
                int ch  = 2 * s + ((lane >> 3) & 1);
                ldsm2(bf[j][0], bf[j][1],
                      bbase + row * 64 + ((ch ^ ((row >> 1) & 3)) << 4));
            }
            #pragma unroll
            for (int i = 0; i < 4; i++)
                #pragma unroll
                for (int j = 0; j < 4; j++)
                    mma_f16(acc[i][j], af[i][0], af[i][1], af[i][2], af[i][3],
                            bf[j][0], bf[j][1]);
        }
    };

    const int CH = K / 32;
    issue(0, 0);
    asm volatile("cp.async.commit_group;" ::: "memory");
    issue(1, 32);
    asm volatile("cp.async.commit_group;" ::: "memory");
    for (int c = 0; c < CH; c++) {
        asm volatile("cp.async.wait_group 1;" ::: "memory");
        __syncthreads();
        if (c + 2 < CH) issue((c + 2) % 3, (c + 2) * 32);
        asm volatile("cp.async.commit_group;" ::: "memory");
        compute(c % 3);
    }

    #pragma unroll
    for (int i = 0; i < 4; i++)
        #pragma unroll
        for (int j = 0; j < 4; j++) {
            int col = wn * 32 + j * 8 + 2 * (lane & 3);
            #pragma unroll
            for (int h = 0; h < 2; h++) {
                int row = wm * 64 + i * 16 + (lane >> 2) + h * 8;
                __half2 hv = __floats2half2_rn(acc[i][j][h * 2], acc[i][j][h * 2 + 1]);
                *(uint32_t*)(Ch + (size_t)(by * 128 + row) * Nn + bx * 128 + col) = *(uint32_t*)&hv;
            }
        }
}

// ---------------------------------------------------------------------------
// Fused GEMM2+GEMM3: out = leaky(leaky(o1@W1+b1)@W2+b2), h1 kept in smem.
// smem: h1buf 64KB (128 rows x 512B, swizzle chunk^(row&7)) + 48KB stages.
// 2 CTAs/SM: 2 x 112KB = 224KB <= 228KB, regs capped at 128.
// ---------------------------------------------------------------------------
constexpr int H1_BYTES   = 128 * 512;                 // 65536
constexpr int F23_SMEM   = H1_BYTES + GEMM_SMEM;      // 114688

__global__ __launch_bounds__(256, 2)
void fused23_kernel(const __half* __restrict__ o1h, const __half* __restrict__ w1h,
                    const __half* __restrict__ w2h, const float* __restrict__ b1,
                    const float* __restrict__ b2, float* __restrict__ out) {
    extern __shared__ uint32_t sh[];

    const int tid  = threadIdx.x;
    const int lane = tid & 31;
    const int wid  = tid >> 5;
    const int wm   = wid & 1;
    const int wn   = wid >> 1;
    const int by = blockIdx.x;

    const uint32_t sbase  = (uint32_t)__cvta_generic_to_shared(sh);
    const uint32_t h1base = sbase;
    const uint32_t stbase = sbase + H1_BYTES;
    const int sRow = tid >> 1;
    const int sC2  = (tid & 1) * 2;

    float acc[4][4][4];

    const __half* Ablk = o1h + (size_t)by * 128 * F;

    // ---------------- Phase 1: h1 = leaky(o1 @ W1 + b1) -> smem ----------------
    #pragma unroll 1
    for (int half = 0; half < 2; half++) {
        #pragma unroll
        for (int i = 0; i < 4; i++)
            #pragma unroll
            for (int j = 0; j < 4; j++)
                #pragma unroll
                for (int q = 0; q < 4; q++) acc[i][j][q] = 0.0f;

        const __half* Bblk = w1h + (size_t)half * 128 * F;

        auto issue1 = [&](int st, int kt) {
            uint32_t abase = stbase + st * STAGE_BYTES;
            uint32_t bbase = abase + 8192;
            #pragma unroll
            for (int q = 0; q < 2; q++) {
                int c = sC2 + q;
                uint32_t doff = sRow * 64 + ((c ^ ((sRow >> 1) & 3)) << 4);
                asm volatile("cp.async.cg.shared.global [%0], [%1], 16;"
                             :: "r"(abase + doff), "l"(Ablk + (size_t)sRow * F + kt + c * 8));
                asm volatile("cp.async.cg.shared.global [%0], [%1], 16;"
                             :: "r"(bbase + doff), "l"(Bblk + (size_t)sRow * F + kt + c * 8));
            }
        };
        auto compute1 = [&](int st) {
            uint32_t abase = stbase + st * STAGE_BYTES;
            uint32_t bbase = abase + 8192;
            #pragma unroll
            for (int s = 0; s < 2; s++) {
                uint32_t af[4][4], bf[4][2];
                #pragma unroll
                for (int i = 0; i < 4; i++) {
                    int row = wm * 64 + i * 16 + (lane & 7) + ((lane >> 3) & 1) * 8;
                    int ch  = 2 * s + (lane >> 4);
                    ldsm4(af[i][0], af[i][1], af[i][2], af[i][3],
                          abase + row * 64 + ((ch ^ ((row >> 1) & 3)) << 4));
                }
                #pragma unroll
                for (int j = 0; j < 4; j++) {
                    int row = wn * 32 + j * 8 + (lane & 7);
                    int ch  = 2 * s + ((lane >> 3) & 1);
                    ldsm2(bf[j][0], bf[j][1],
                          bbase + row * 64 + ((ch ^ ((row >> 1) & 3)) << 4));
                }
                #pragma unroll
                for (int i = 0; i < 4; i++)
                    #pragma unroll
                    for (int j = 0; j < 4; j++)
                        mma_f16(acc[i][j], af[i][0], af[i][1], af[i][2], af[i][3],
                                bf[j][0], bf[j][1]);
            }
        };

        issue1(0, 0);
        asm volatile("cp.async.commit_group;" ::: "memory");
        issue1(1, 32);
        asm volatile("cp.async.commit_group;" ::: "memory");
        for (int c = 0; c < 4; c++) {
            asm volatile("cp.async.wait_group 1;" ::: "memory");
            __syncthreads();
            if (c + 2 < 4) issue1((c + 2) % 3, (c + 2) * 32);
            asm volatile("cp.async.commit_group;" ::: "memory");
            compute1(c % 3);
        }
        __syncthreads();   // stages fully consumed before reuse / h1 writes ordered

        // epilogue -> smem h1buf (fp16, swizzle ch ^ (row&7) on 512B rows)
        #pragma unroll
        for (int i = 0; i < 4; i++)
            #pragma unroll
            for (int j = 0; j < 4; j++) {
                int gcol = half * 128 + wn * 32 + j * 8 + 2 * (lane & 3);
                int ch16 = gcol >> 3;
                float bx0 = b1[gcol], bx1 = b1[gcol + 1];
                #pragma unroll
                for (int h = 0; h < 2; h++) {
                    int row = wm * 64 + i * 16 + (lane >> 2) + h * 8;
                    float vx = acc[i][j][h * 2] + bx0;
                    float vy = acc[i][j][h * 2 + 1] + bx1;
                    vx = vx > 0.0f ? vx : NEG_SLOPE * vx;
                    vy = vy > 0.0f ? vy : NEG_SLOPE * vy;
                    __half2 hv = __floats2half2_rn(vx, vy);
                    uint32_t addr = h1base + row * 512 + ((ch16 ^ (row & 7)) << 4)
                                  + (gcol & 7) * 2;
                    asm volatile("st.shared.b32 [%0], %1;" :: "r"(addr), "r"(*(uint32_t*)&hv));
                }
            }
        __syncthreads();
    }

    // ---------------- Phase 2: out = leaky(h1 @ W2 + b2) ----------------
    #pragma unroll 1
    for (int outhalf = 0; outhalf < 2; outhalf++) {
        #pragma unroll
        for (int i = 0; i < 4; i++)
            #pragma unroll
            for (int j = 0; j < 4; j++)
                #pragma unroll
                for (int q = 0; q < 4; q++) acc[i][j][q] = 0.0f;

        const __half* Bblk = w2h + (size_t)outhalf * 128 * H;

        auto issue2 = [&](int st, int kt) {
            uint32_t bbase = stbase + st * STAGE_BYTES;   // B-only stage
            #pragma unroll
            for (int q = 0; q < 2; q++) {
                int c = sC2 + q;
                uint32_t doff = sRow * 64 + ((c ^ ((sRow >> 1) & 3)) << 4);
                asm volatile("cp.async.cg.shared.global [%0], [%1], 16;"
                             :: "r"(bbase + doff), "l"(Bblk + (size_t)sRow * H + kt + c * 8));
            }
        };
        auto compute2 = [&](int st, int kc) {
            uint32_t bbase = stbase + st * STAGE_BYTES;
            #pragma unroll
            for (int s = 0; s < 2; s++) {
                uint32_t af[4][4], bf[4][2];
                #pragma unroll
                for (int i = 0; i < 4; i++) {
                    int row = wm * 64 + i * 16 + (lane & 7) + ((lane >> 3) & 1) * 8;
                    int ch  = kc * 4 + 2 * s + (lane >> 4);
                    ldsm4(af[i][0], af[i][1], af[i][2], af[i][3],
                          h1base + row * 512 + ((ch ^ (row & 7)) << 4));
                }
                #pragma unroll
                for (int j = 0; j < 4; j++) {
                    int row = wn * 32 + j * 8 + (lane & 7);
                    int ch  = 2 * s + ((lane >> 3) & 1);
                    ldsm2(bf[j][0], bf[j][1],
                          bbase + row * 64 + ((ch ^ ((row >> 1) & 3)) << 4));
                }
                #pragma unroll
                for (int i = 0; i < 4; i++)
                    #pragma unroll
                    for (int j = 0; j < 4; j++)
                        mma_f16(acc[i][j], af[i][0], af[i][1], af[i][2], af[i][3],
                                bf[j][0], bf[j][1]);
            }
        };

        issue2(0, 0);
        asm volatile("cp.async.commit_group;" ::: "memory");
        issue2(1, 32);
        asm volatile("cp.async.commit_group;" ::: "memory");
        for (int c = 0; c < 8; c++) {
            asm volatile("cp.async.wait_group 1;" ::: "memory");
            __syncthreads();
            if (c + 2 < 8) issue2((c + 2) % 3, (c + 2) * 32);
            asm volatile("cp.async.commit_group;" ::: "memory");
            compute2(c % 3, c);
        }
        __syncthreads();

        #pragma unroll
        for (int i = 0; i < 4; i++)
            #pragma unroll
            for (int j = 0; j < 4; j++) {
                int gcol = outhalf * 128 + wn * 32 + j * 8 + 2 * (lane & 3);
                float bx0 = b2[gcol], bx1 = b2[gcol + 1];
                #pragma unroll
                for (int h = 0; h < 2; h++) {
                    int row = wm * 64 + i * 16 + (lane >> 2) + h * 8;
                    float vx = acc[i][j][h * 2] + bx0;
                    float vy = acc[i][j][h * 2 + 1] + bx1;
                    vx = vx > 0.0f ? vx : NEG_SLOPE * vx;
                    vy = vy > 0.0f ? vy : NEG_SLOPE * vy;
                    *(float2*)(out + (size_t)(by * 128 + row) * H + gcol) = make_float2(vx, vy);
                }
            }
    }
}

// ---------------------------------------------------------------------------
// Gather-aggregate + fused post: one warp per dst row.
// ---------------------------------------------------------------------------
__global__ __launch_bounds__(256)
void gather_kernel(const float* __restrict__ bc) {
    int w = (blockIdx.x * blockDim.x + threadIdx.x) >> 5;
    int lane = threadIdx.x & 31;
    if (w >= BNN) return;

    float dd = g_dinv[w];
    float selfs = dd * dd;
    uint2 sv = ((const uint2*)(g_xwh + (size_t)w * F))[lane];
    float2 s01 = __half22float2(*(__half2*)&sv.x);
    float2 s23 = __half22float2(*(__half2*)&sv.y);
    float a0 = selfs * s01.x, a1 = selfs * s01.y;
    float a2 = selfs * s23.x, a3 = selfs * s23.y;

    int kbeg = g_rowoff[w];
    int kend = (w + 1 < BNN) ? g_rowoff[w + 1] : BE;
    for (int k = kbeg; k < kend; k++) {
        int gs = g_csr_src[k];
        float nm = g_csr_norm[k];
        uint2 v = ((const uint2*)(g_xwh + (size_t)gs * F))[lane];
        float2 f01 = __half22float2(*(__half2*)&v.x);
        float2 f23 = __half22float2(*(__half2*)&v.y);
        a0 = fmaf(nm, f01.x, a0);
        a1 = fmaf(nm, f01.y, a1);
        a2 = fmaf(nm, f23.x, a2);
        a3 = fmaf(nm, f23.y, a3);
    }

    float4 bb = ((const float4*)bc)[lane];
    uint2 xh = ((const uint2*)(g_x0h + (size_t)w * F))[lane];
    float2 x01 = __half22float2(*(__half2*)&xh.x);
    float2 x23 = __half22float2(*(__half2*)&xh.y);
    float o0 = fmaxf(a0 + bb.x, 0.0f) + x01.x;
    float o1 = fmaxf(a1 + bb.y, 0.0f) + x01.y;
    float o2 = fmaxf(a2 + bb.z, 0.0f) + x23.x;
    float o3 = fmaxf(a3 + bb.w, 0.0f) + x23.y;
    __half2 h01 = __floats2half2_rn(o0, o1);
    __half2 h23 = __floats2half2_rn(o2, o3);
    uint2 st;
    st.x = *(uint32_t*)&h01;
    st.y = *(uint32_t*)&h23;
    ((uint2*)(g_o1h + (size_t)w * F))[lane] = st;
}

// ---------------------------------------------------------------------------
extern "C" void kernel_launch(void* const* d_in, const int* in_sizes, int n_in,
                              void* d_out, int out_size) {
    const float* x0 = (const float*)d_in[0];       // [B,N,F]
    const int*   ei = (const int*)d_in[1];         // [B,2,E] int32
    const float* Wc = (const float*)d_in[2];       // [F,F]
    const float* bc = (const float*)d_in[3];       // [F]
    const float* W1 = (const float*)d_in[4];       // [F,H]
    const float* b1 = (const float*)d_in[5];       // [H]
    const float* W2 = (const float*)d_in[6];       // [H,H]
    const float* b2 = (const float*)d_in[7];       // [H]
    float* out = (float*)d_out;                    // [B,N,H]

    __half *xwh, *x0h, *o1h, *wch, *w1h, *w2h;
    cudaGetSymbolAddress((void**)&xwh,  g_xwh);
    cudaGetSymbolAddress((void**)&x0h,  g_x0h);
    cudaGetSymbolAddress((void**)&o1h,  g_o1h);
    cudaGetSymbolAddress((void**)&wch,  g_wch);
    cudaGetSymbolAddress((void**)&w1h,  g_w1h);
    cudaGetSymbolAddress((void**)&w2h,  g_w2h);

    static bool init_done = false;
    static cudaStream_t s1;
    static cudaEvent_t evFork, evJoin;
    if (!init_done) {
        cudaFuncSetAttribute(f16_gemm_kernel, cudaFuncAttributeMaxDynamicSharedMemorySize, GEMM_SMEM);
        cudaFuncSetAttribute(fused23_kernel, cudaFuncAttributeMaxDynamicSharedMemorySize, F23_SMEM);
        cudaStreamCreateWithFlags(&s1, cudaStreamNonBlocking);
        cudaEventCreateWithFlags(&evFork, cudaEventDisableTiming);
        cudaEventCreateWithFlags(&evJoin, cudaEventDisableTiming);
        init_done = true;
    }

    // Fork: CSR build chain on s1 (depends only on edge_index)
    cudaEventRecord(evFork, 0);
    cudaStreamWaitEvent(s1, evFork, 0);
    zero_deg_kernel<<<NBLK, 256, 0, s1>>>();
    hist_kernel<<<(BE + 255) / 256, 256, 0, s1>>>(ei);
    dinv_kernel<<<NBLK, 256, 0, s1>>>();
    scan1_kernel<<<NBLK, 256, 0, s1>>>();
    scan2_kernel<<<1, 512, 0, s1>>>();
    scan3_kernel<<<NBLK, 256, 0, s1>>>();
    fill_kernel<<<(BE + 255) / 256, 256, 0, s1>>>(ei);
    cudaEventRecord(evJoin, s1);

    // Main chain: weight/input conversion, then GEMM1
    transpose_f16_kernel<<<(F * F + 255) / 256, 256>>>(Wc, wch, F, F);
    transpose_f16_kernel<<<(F * H + 255) / 256, 256>>>(W1, w1h, F, H);
    transpose_f16_kernel<<<(H * H + 255) / 256, 256>>>(W2, w2h, H, H);
    cvt_f16_kernel<<<(BNN * F / 4 + 255) / 256, 256>>>(x0, x0h, BNN * F / 4);
    {
        dim3 grid(1, BNN / 128);
        f16_gemm_kernel<<<grid, 256, GEMM_SMEM>>>(x0h, wch, xwh, BNN, F, F);
    }

    // Join: gather needs CSR (s1) + xwh (stream 0)
    cudaStreamWaitEvent(0, evJoin, 0);
    gather_kernel<<<(BNN * 32 + 255) / 256, 256>>>(bc);

    // Fused GEMM2+GEMM3
    fused23_kernel<<<BNN / 128, 256, F23_SMEM>>>(o1h, w1h, w2h, b1, b2, out);
}